// round 11
// baseline (speedup 1.0000x reference)
#include <cuda_runtime.h>
#include <cuda_bf16.h>
#include <math.h>
#include <stdint.h>

#define B_    32
#define T_    1024
#define H_    1024
#define FH_   4096
#define DIN_  256
#define DOUT_ 512
#define BT_   (B_*T_)
#define NBLK_ 128
#define NTH_L 512            // recurrence block: 16 warps, 4/SMSP

// -------- scratch (static device globals; no allocation anywhere) ----------
__device__ float g_XZ[(size_t)BT_*FH_];        // 512 MB, xz for current layer
__device__ __nv_bfloat16 g_Hh[(size_t)BT_*H_]; // layer output hi (reused L1 then L2)
__device__ __nv_bfloat16 g_Hl[(size_t)BT_*H_]; // layer output lo
__device__ __nv_bfloat16 g_hA[2][64*1024];     // step mirror: rows 0-31 h_hi, 32-63 h_lo
// converted operands
__device__ __nv_bfloat16 g_obs_h[(size_t)BT_*DIN_], g_obs_l[(size_t)BT_*DIN_];
__device__ __nv_bfloat16 g_W1x_h[(size_t)DIN_*FH_], g_W1x_l[(size_t)DIN_*FH_];
__device__ __nv_bfloat16 g_W2x_h[(size_t)H_*FH_],   g_W2x_l[(size_t)H_*FH_];
__device__ __nv_bfloat16 g_Wm_h[(size_t)H_*DOUT_],  g_Wm_l[(size_t)H_*DOUT_];
__device__ __nv_bfloat16 g_Wc_h[(size_t)H_*DOUT_],  g_Wc_l[(size_t)H_*DOUT_];

// grid barrier (generation-relative => safe across graph replays)
__device__ unsigned          g_bar_count = 0;
__device__ volatile unsigned g_bar_gen   = 0;

__device__ __forceinline__ void grid_sync(unsigned* gen_local)
{
    __syncthreads();
    if (threadIdx.x == 0) {
        unsigned my = *gen_local;
        __threadfence();
        unsigned arr = atomicAdd(&g_bar_count, 1u);
        if (arr == NBLK_ - 1) {
            g_bar_count = 0;
            __threadfence();
            g_bar_gen = my + 1;
        } else {
            while (g_bar_gen == my) { }
        }
        *gen_local = my + 1;
    }
    __syncthreads();
}

// ---- cp.async helpers -----------------------------------------------------
__device__ __forceinline__ void cp_async16(void* sptr, const void* gptr)
{
    unsigned sa = (unsigned)__cvta_generic_to_shared(sptr);
    asm volatile("cp.async.cg.shared.global [%0], [%1], 16;" :: "r"(sa), "l"(gptr));
}
__device__ __forceinline__ void cp_commit()
{
    asm volatile("cp.async.commit_group;" ::: "memory");
}
template<int N> __device__ __forceinline__ void cp_wait()
{
    asm volatile("cp.async.wait_group %0;" :: "n"(N) : "memory");
}

// ---- warp-MMA helpers -----------------------------------------------------
__device__ __forceinline__ uint32_t smem_u32(const void* p)
{
    uint32_t a;
    asm("{ .reg .u64 t; cvta.to.shared.u64 t, %1; cvt.u32.u64 %0, t; }" : "=r"(a) : "l"(p));
    return a;
}
__device__ __forceinline__ void ldsm_x4(uint32_t& r0, uint32_t& r1, uint32_t& r2, uint32_t& r3,
                                        uint32_t addr)
{
    asm volatile("ldmatrix.sync.aligned.m8n8.x4.shared.b16 {%0,%1,%2,%3}, [%4];"
                 : "=r"(r0), "=r"(r1), "=r"(r2), "=r"(r3) : "r"(addr));
}
__device__ __forceinline__ void ldsm_x4t(uint32_t& r0, uint32_t& r1, uint32_t& r2, uint32_t& r3,
                                         uint32_t addr)
{
    asm volatile("ldmatrix.sync.aligned.m8n8.x4.trans.shared.b16 {%0,%1,%2,%3}, [%4];"
                 : "=r"(r0), "=r"(r1), "=r"(r2), "=r"(r3) : "r"(addr));
}
__device__ __forceinline__ void mma16816(float* d,
                                         uint32_t a0, uint32_t a1, uint32_t a2, uint32_t a3,
                                         uint32_t b0, uint32_t b1)
{
    asm volatile("mma.sync.aligned.m16n8k16.row.col.f32.bf16.bf16.f32 "
                 "{%0,%1,%2,%3}, {%4,%5,%6,%7}, {%8,%9}, {%0,%1,%2,%3};"
                 : "+f"(d[0]), "+f"(d[1]), "+f"(d[2]), "+f"(d[3])
                 : "r"(a0), "r"(a1), "r"(a2), "r"(a3), "r"(b0), "r"(b1));
}

// recurrence swizzles (validated R9)
#define SW_B(k, nb) ((uint32_t)(k) * 64u + (uint32_t)((((nb) ^ (((k) >> 1) & 3))) * 16))
#define SW_A(m, unit) ((uint32_t)(m) * 512u + (uint32_t)((((unit) ^ ((m) & 7))) * 16))

// ---- recurrence smem layout (bytes) ---------------------------------------
#define SO_WHI   0
#define SO_WLO   65536
#define SO_A     131072          // 2 x 32768
#define SO_Z     196608          // [2 kh][64][33] f32 = 16896
#define SMEM_R   213504

// ---------------------------------------------------------------------------
// fp32 -> bf16 hi/lo conversion (vectorized by 4)
// ---------------------------------------------------------------------------
__global__ void conv_hl(const float* __restrict__ src, __nv_bfloat16* __restrict__ hi,
                        __nv_bfloat16* __restrict__ lo, int n4)
{
    int i = blockIdx.x * blockDim.x + threadIdx.x;
    if (i < n4) {
        float4 v = ((const float4*)src)[i];
        __nv_bfloat16 h[4], l[4];
        float vv[4] = {v.x, v.y, v.z, v.w};
        #pragma unroll
        for (int j = 0; j < 4; j++) {
            h[j] = __float2bfloat16(vv[j]);
            l[j] = __float2bfloat16(vv[j] - __bfloat162float(h[j]));
        }
        ((uint64_t*)hi)[i] = *(uint64_t*)h;
        ((uint64_t*)lo)[i] = *(uint64_t*)l;
    }
}

// ---------------------------------------------------------------------------
// bf16 hi/lo GEMM (unchanged R10): C = (Ahi+Alo)@(Bhi+Blo) + bias, 3-term.
// ---------------------------------------------------------------------------
template<int EPI>
__global__ __launch_bounds__(256, 2)
void gemm_bf16_hl(const __nv_bfloat16* __restrict__ Ahi, const __nv_bfloat16* __restrict__ Alo,
                  const __nv_bfloat16* __restrict__ Bhi, const __nv_bfloat16* __restrict__ Blo,
                  const float* __restrict__ bias, float* __restrict__ C,
                  int M, int N, int K, int ldc)
{
    __shared__ __align__(128) char sm[32768];
    const uint32_t sA = smem_u32(sm);
    const uint32_t sB = sA + 24576;

    const int tid  = threadIdx.x;
    const int wid  = tid >> 5;
    const int lane = tid & 31;
    const int mt   = wid >> 1;
    const int nh   = wid & 1;
    const int bm   = blockIdx.y * 128;
    const int bn   = blockIdx.x * 64;

    const int arow0 = mt * 32 + (lane & 7) + ((lane >> 3) & 1) * 8;
    const int a_u   = lane >> 4;
    const int kr    = lane & 15;
    const int nb0   = nh * 4 + (lane >> 4);
    const int nb1   = nh * 4 + 2 + (lane >> 4);

    float d[2][2][2][4];
    #pragma unroll
    for (int q = 0; q < 2; q++)
        #pragma unroll
        for (int s = 0; s < 2; s++)
            #pragma unroll
            for (int h8 = 0; h8 < 2; h8++)
                #pragma unroll
                for (int e = 0; e < 4; e++) d[q][s][h8][e] = 0.f;

    const int nk = K / 16;

    {
        #pragma unroll
        for (int i = 0; i < 2; i++) {
            int idx = tid + i * 256;
            int hl = idx >> 8, rem = idx & 255;
            int r = rem >> 1, u = rem & 1;
            const __nv_bfloat16* src = (hl ? Alo : Ahi) + (size_t)(bm + r) * K + u * 8;
            cp_async16(sm + hl * 6144 + r * 48 + u * 16, src);
        }
        {
            int hl = tid >> 7, rem = tid & 127;
            int kk = rem >> 3, nb = rem & 7;
            const __nv_bfloat16* src = (hl ? Blo : Bhi) + (size_t)kk * N + bn + nb * 8;
            cp_async16(sm + 24576 + hl * 2048 + kk * 128 + ((nb ^ (kk & 7)) * 16), src);
        }
        cp_commit();
    }

    for (int c = 0; c < nk; c++) {
        const int buf = c & 1;
        cp_wait<0>();
        __syncthreads();

        if (c + 1 < nk) {
            const int k0 = (c + 1) * 16;
            char* base = (char*)sm + ((buf ^ 1) ? 12288 : 0);
            #pragma unroll
            for (int i = 0; i < 2; i++) {
                int idx = tid + i * 256;
                int hl = idx >> 8, rem = idx & 255;
                int r = rem >> 1, u = rem & 1;
                const __nv_bfloat16* src = (hl ? Alo : Ahi) + (size_t)(bm + r) * K + k0 + u * 8;
                cp_async16(base + hl * 6144 + r * 48 + u * 16, src);
            }
            {
                int hl = tid >> 7, rem = tid & 127;
                int kk = rem >> 3, nb = rem & 7;
                const __nv_bfloat16* src = (hl ? Blo : Bhi) + (size_t)(k0 + kk) * N + bn + nb * 8;
                cp_async16((char*)sm + 24576 + ((buf ^ 1) ? 4096 : 0) + hl * 2048
                           + kk * 128 + ((nb ^ (kk & 7)) * 16), src);
            }
            cp_commit();
        }

        const uint32_t aB = sA + buf * 12288;
        const uint32_t bB = sB + buf * 4096;

        uint32_t ah[2][4], al[2][4], bh[2][4], bl[2][4];
        #pragma unroll
        for (int q = 0; q < 2; q++) {
            uint32_t ra = aB + (uint32_t)(arow0 + q * 16) * 48 + a_u * 16;
            ldsm_x4(ah[q][0], ah[q][1], ah[q][2], ah[q][3], ra);
            ldsm_x4(al[q][0], al[q][1], al[q][2], al[q][3], ra + 6144);
        }
        {
            uint32_t r0 = bB + (uint32_t)kr * 128 + ((nb0 ^ (kr & 7)) * 16);
            uint32_t r1 = bB + (uint32_t)kr * 128 + ((nb1 ^ (kr & 7)) * 16);
            ldsm_x4t(bh[0][0], bh[0][1], bh[0][2], bh[0][3], r0);
            ldsm_x4t(bh[1][0], bh[1][1], bh[1][2], bh[1][3], r1);
            ldsm_x4t(bl[0][0], bl[0][1], bl[0][2], bl[0][3], r0 + 2048);
            ldsm_x4t(bl[1][0], bl[1][1], bl[1][2], bl[1][3], r1 + 2048);
        }

        #pragma unroll
        for (int q = 0; q < 2; q++)
            #pragma unroll
            for (int s = 0; s < 2; s++) {
                mma16816(d[q][s][0], ah[q][0], ah[q][1], ah[q][2], ah[q][3], bh[s][0], bh[s][1]);
                mma16816(d[q][s][1], ah[q][0], ah[q][1], ah[q][2], ah[q][3], bh[s][2], bh[s][3]);
                mma16816(d[q][s][0], ah[q][0], ah[q][1], ah[q][2], ah[q][3], bl[s][0], bl[s][1]);
                mma16816(d[q][s][1], ah[q][0], ah[q][1], ah[q][2], ah[q][3], bl[s][2], bl[s][3]);
                mma16816(d[q][s][0], al[q][0], al[q][1], al[q][2], al[q][3], bh[s][0], bh[s][1]);
                mma16816(d[q][s][1], al[q][0], al[q][1], al[q][2], al[q][3], bh[s][2], bh[s][3]);
            }
        __syncthreads();
    }

    #pragma unroll
    for (int q = 0; q < 2; q++) {
        int row = bm + mt * 32 + q * 16 + (lane >> 2);
        #pragma unroll
        for (int s = 0; s < 2; s++) {
            #pragma unroll
            for (int h8 = 0; h8 < 2; h8++) {
                int col = bn + nh * 32 + s * 16 + h8 * 8 + (lane & 3) * 2;
                float b0 = bias[col], b1 = bias[col + 1];
                float v0 = d[q][s][h8][0] + b0;
                float v1 = d[q][s][h8][1] + b1;
                float v2 = d[q][s][h8][2] + b0;
                float v3 = d[q][s][h8][3] + b1;
                if (EPI == 1) {
                    v0 = (v0 > 20.f) ? v0 : log1pf(expf(v0));
                    v1 = (v1 > 20.f) ? v1 : log1pf(expf(v1));
                    v2 = (v2 > 20.f) ? v2 : log1pf(expf(v2));
                    v3 = (v3 > 20.f) ? v3 : log1pf(expf(v3));
                }
                *(float2*)&C[(size_t)row * ldc + col]       = make_float2(v0, v1);
                *(float2*)&C[(size_t)(row + 8) * ldc + col] = make_float2(v2, v3);
            }
        }
    }
}

// ---------------------------------------------------------------------------
// Persistent warp-MMA LSTM layer v5: 512 threads (16 warps, 4/SMSP).
// warp = (kh 0-1, mt 0-3, nh 0-1): kh splits each phase's k range in half,
// doubling issue parallelism to hide ldsm/mma latency. Partials summed via
// zb[2][64][33]. Epilogue/c-state: threads < 256, thread = (b, u) pair.
// ---------------------------------------------------------------------------
__global__ __launch_bounds__(NTH_L, 1)
void lstm_layer_mma(const float* __restrict__ Wh,   // [H, 4H]
                    const float* __restrict__ XZ)   // [B*T, 4H] (bias folded)
{
    extern __shared__ __align__(128) char smem[];
    const uint32_t sbase = smem_u32(smem);
    const uint32_t sWHI  = sbase + SO_WHI;
    const uint32_t sWLO  = sbase + SO_WLO;
    const uint32_t sA    = sbase + SO_A;
    float* zb = (float*)(smem + SO_Z);    // [2][64][33]

    const int tid  = threadIdx.x;
    const int wid  = tid >> 5;
    const int lane = tid & 31;
    const int u0   = blockIdx.x * 8;

    // epilogue identity (threads < 256)
    const int eb = (tid >> 3) & 31;
    const int ej = tid & 7;
    const size_t hrow = (size_t)eb * T_;

    // ---- one-time: W slice -> bf16 hi/lo, swizzled. col(n) = (n>>3)*H + u0 + (n&7)
    for (int idx = tid; idx < 32 * 1024; idx += NTH_L) {
        int n = idx & 31, k = idx >> 5;
        int gcol = (n >> 3) * H_ + u0 + (n & 7);
        float w = Wh[(size_t)k * FH_ + gcol];
        __nv_bfloat16 hi = __float2bfloat16(w);
        __nv_bfloat16 lo = __float2bfloat16(w - __bfloat162float(hi));
        uint32_t off = SW_B(k, n >> 3) + (uint32_t)(n & 7) * 2;
        *(__nv_bfloat16*)(smem + SO_WHI + off) = hi;
        *(__nv_bfloat16*)(smem + SO_WLO + off) = lo;
    }

    float c_reg = 0.f;

    unsigned gen_local = 0;
    if (tid == 0) gen_local = g_bar_gen;

    // =========================== t = 0 (h0 = 0) ============================
    if (tid < 256) {
        const float* xzp = XZ + hrow * FH_ + u0 + ej;
        float zi = __ldg(&xzp[0]);
        float zg = __ldg(&xzp[2 * H_]);
        float zo = __ldg(&xzp[3 * H_]);
        float iv = 1.f / (1.f + __expf(-zi));
        float eg = __expf(-2.f * zg); float gv = (1.f - eg) / (1.f + eg);
        float ov = 1.f / (1.f + __expf(-zo));
        c_reg = iv * gv;
        float ec = __expf(-2.f * c_reg); float tc = (1.f - ec) / (1.f + ec);
        float hv = ov * tc;
        __nv_bfloat16 hi = __float2bfloat16(hv);
        __nv_bfloat16 lo = __float2bfloat16(hv - __bfloat162float(hi));
        g_Hh[hrow * H_ + u0 + ej] = hi;
        g_Hl[hrow * H_ + u0 + ej] = lo;
        g_hA[0][(size_t)eb * 1024 + u0 + ej]        = hi;
        g_hA[0][(size_t)(eb + 32) * 1024 + u0 + ej] = lo;
    }
    __threadfence();
    grid_sync(&gen_local);

    // warp tiling: warp = (kh 0-1, mt 0-3, nh 0-1)
    const int kh  = wid >> 3;
    const int wr  = wid & 7;
    const int mt  = wr >> 1;
    const int nh  = wr & 1;
    const int m_loc = mt * 16 + (lane & 7) + ((lane >> 3) & 1) * 8;
    const int krow  = (lane & 7) + ((lane >> 3) & 1) * 8;
    const int nb    = nh * 2 + (lane >> 4);
    const int uoff  = lane >> 4;
    float* zbk = zb + kh * 2112;         // [64][33] for this kh

    // =========================== main loop =================================
    for (int t = 1; t < T_; t++) {
        const __nv_bfloat16* hA = g_hA[(t - 1) & 1];

        // stage phase 0 -> buf0 (64 rows x 256 k bf16, swizzled)
        #pragma unroll
        for (int i = 0; i < 4; i++) {
            int g = tid + i * 512;
            int r = g >> 5, cc = g & 31;
            cp_async16(smem + SO_A + SW_A(r, cc),
                       (const char*)hA + (size_t)r * 2048 + (size_t)cc * 16);
        }
        cp_commit();

        // prefetch xz gate inputs straight into registers (epilogue threads)
        float x_i = 0.f, x_f = 0.f, x_g = 0.f, x_o = 0.f;
        if (tid < 256) {
            const float* xzp = XZ + (hrow + t) * FH_ + u0 + ej;
            x_i = __ldg(&xzp[0]);
            x_f = __ldg(&xzp[H_]);
            x_g = __ldg(&xzp[2 * H_]);
            x_o = __ldg(&xzp[3 * H_]);
        }

        float d0[4] = {0.f, 0.f, 0.f, 0.f};
        float d1[4] = {0.f, 0.f, 0.f, 0.f};

        #pragma unroll 1
        for (int p = 0; p < 4; p++) {
            cp_wait<0>();
            __syncthreads();

            if (p < 3) {   // prefetch phase p+1 into other buffer
                const char* src = (const char*)hA + (size_t)(p + 1) * 512;
                char* dstb = smem + SO_A + (size_t)((p + 1) & 1) * 32768;
                #pragma unroll
                for (int i = 0; i < 4; i++) {
                    int g = tid + i * 512;
                    int r = g >> 5, cc = g & 31;
                    cp_async16(dstb + SW_A(r, cc),
                               src + (size_t)r * 2048 + (size_t)cc * 16);
                }
                cp_commit();
            }

            const uint32_t abase = sA + (uint32_t)(p & 1) * 32768u;
            #pragma unroll
            for (int ks = 0; ks < 8; ks++) {
                const int ksg = kh * 8 + ks;
                uint32_t a0, a1, a2, a3, b0, b1, b2, b3;
                ldsm_x4(a0, a1, a2, a3, abase + SW_A(m_loc, ksg * 2 + uoff));
                int kk = p * 256 + ksg * 16 + krow;
                uint32_t boff = SW_B(kk, nb);
                ldsm_x4t(b0, b1, b2, b3, sWHI + boff);
                mma16816(d0, a0, a1, a2, a3, b0, b1);
                mma16816(d1, a0, a1, a2, a3, b2, b3);
                ldsm_x4t(b0, b1, b2, b3, sWLO + boff);
                mma16816(d0, a0, a1, a2, a3, b0, b1);
                mma16816(d1, a0, a1, a2, a3, b2, b3);
            }
        }

        // ---- d-frags -> zb[kh][64][33]
        {
            int row = mt * 16 + (lane >> 2);
            int col = nh * 16 + (lane & 3) * 2;
            zbk[row * 33 + col]           = d0[0];
            zbk[row * 33 + col + 1]       = d0[1];
            zbk[(row + 8) * 33 + col]     = d0[2];
            zbk[(row + 8) * 33 + col + 1] = d0[3];
            zbk[row * 33 + col + 8]           = d1[0];
            zbk[row * 33 + col + 9]           = d1[1];
            zbk[(row + 8) * 33 + col + 8]     = d1[2];
            zbk[(row + 8) * 33 + col + 9]     = d1[3];
        }
        __syncthreads();

        // ---- gates: threads < 256, one (b, u) each; sum kh and hi/lo rows
        if (tid < 256) {
            float zi = zb[eb * 33 + ej]      + zb[(eb + 32) * 33 + ej]
                     + zb[2112 + eb * 33 + ej]      + zb[2112 + (eb + 32) * 33 + ej]      + x_i;
            float zf = zb[eb * 33 + 8 + ej]  + zb[(eb + 32) * 33 + 8 + ej]
                     + zb[2112 + eb * 33 + 8 + ej]  + zb[2112 + (eb + 32) * 33 + 8 + ej]  + x_f;
            float zg = zb[eb * 33 + 16 + ej] + zb[(eb + 32) * 33 + 16 + ej]
                     + zb[2112 + eb * 33 + 16 + ej] + zb[2112 + (eb + 32) * 33 + 16 + ej] + x_g;
            float zo = zb[eb * 33 + 24 + ej] + zb[(eb + 32) * 33 + 24 + ej]
                     + zb[2112 + eb * 33 + 24 + ej] + zb[2112 + (eb + 32) * 33 + 24 + ej] + x_o;

            float iv = 1.f / (1.f + __expf(-zi));
            float fv = 1.f / (1.f + __expf(-zf));
            float eg = __expf(-2.f * zg); float gv = (1.f - eg) / (1.f + eg);
            float ov = 1.f / (1.f + __expf(-zo));
            c_reg = fv * c_reg + iv * gv;
            float ec = __expf(-2.f * c_reg); float tc = (1.f - ec) / (1.f + ec);
            float hv = ov * tc;

            __nv_bfloat16 hi = __float2bfloat16(hv);
            __nv_bfloat16 lo = __float2bfloat16(hv - __bfloat162float(hi));
            g_Hh[(hrow + t) * H_ + u0 + ej] = hi;
            g_Hl[(hrow + t) * H_ + u0 + ej] = lo;
            g_hA[t & 1][(size_t)eb * 1024 + u0 + ej]        = hi;
            g_hA[t & 1][(size_t)(eb + 32) * 1024 + u0 + ej] = lo;
        }

        __threadfence();
        grid_sync(&gen_local);
    }
}

// ---------------------------------------------------------------------------
extern "C" void kernel_launch(void* const* d_in, const int* in_sizes, int n_in,
                              void* d_out, int out_size)
{
    const float* obs = (const float*)d_in[0];
    const float* W1x = (const float*)d_in[1];
    const float* W1h = (const float*)d_in[2];
    const float* b1  = (const float*)d_in[3];
    const float* W2x = (const float*)d_in[4];
    const float* W2h = (const float*)d_in[5];
    const float* b2  = (const float*)d_in[6];
    const float* Wm  = (const float*)d_in[7];
    const float* bm  = (const float*)d_in[8];
    const float* Wc  = (const float*)d_in[9];
    const float* bc  = (const float*)d_in[10];

    float* XZ;
    __nv_bfloat16 *Hh, *Hl, *obsh, *obsl, *w1xh, *w1xl, *w2xh, *w2xl, *wmh, *wml, *wch, *wcl;
    cudaGetSymbolAddress((void**)&XZ,   g_XZ);
    cudaGetSymbolAddress((void**)&Hh,   g_Hh);
    cudaGetSymbolAddress((void**)&Hl,   g_Hl);
    cudaGetSymbolAddress((void**)&obsh, g_obs_h);
    cudaGetSymbolAddress((void**)&obsl, g_obs_l);
    cudaGetSymbolAddress((void**)&w1xh, g_W1x_h);
    cudaGetSymbolAddress((void**)&w1xl, g_W1x_l);
    cudaGetSymbolAddress((void**)&w2xh, g_W2x_h);
    cudaGetSymbolAddress((void**)&w2xl, g_W2x_l);
    cudaGetSymbolAddress((void**)&wmh,  g_Wm_h);
    cudaGetSymbolAddress((void**)&wml,  g_Wm_l);
    cudaGetSymbolAddress((void**)&wch,  g_Wc_h);
    cudaGetSymbolAddress((void**)&wcl,  g_Wc_l);

    float* out = (float*)d_out;
    size_t half = (size_t)out_size / 2;   // mean | cov

    cudaFuncSetAttribute(lstm_layer_mma,
                         cudaFuncAttributeMaxDynamicSharedMemorySize, SMEM_R);

    // ---- conversions (fp32 -> bf16 hi/lo)
    conv_hl<<<(BT_*DIN_/4 + 255)/256, 256>>>(obs, obsh, obsl, BT_*DIN_/4);
    conv_hl<<<(DIN_*FH_/4 + 255)/256, 256>>>(W1x, w1xh, w1xl, DIN_*FH_/4);
    conv_hl<<<(H_*FH_/4   + 255)/256, 256>>>(W2x, w2xh, w2xl, H_*FH_/4);
    conv_hl<<<(H_*DOUT_/4 + 255)/256, 256>>>(Wm,  wmh,  wml,  H_*DOUT_/4);
    conv_hl<<<(H_*DOUT_/4 + 255)/256, 256>>>(Wc,  wch,  wcl,  H_*DOUT_/4);

    // XZ1 = obs @ W1x + b1
    gemm_bf16_hl<0><<<dim3(FH_/64, BT_/128), 256>>>(obsh, obsl, w1xh, w1xl, b1, XZ,
                                                    BT_, FH_, DIN_, FH_);

    // Layer 1 recurrence -> g_Hh/g_Hl = H1
    lstm_layer_mma<<<NBLK_, NTH_L, SMEM_R>>>(W1h, XZ);

    // XZ2 = H1 @ W2x + b2
    gemm_bf16_hl<0><<<dim3(FH_/64, BT_/128), 256>>>(Hh, Hl, w2xh, w2xl, b2, XZ,
                                                    BT_, FH_, H_, FH_);

    // Layer 2 recurrence -> g_Hh/g_Hl = H2
    lstm_layer_mma<<<NBLK_, NTH_L, SMEM_R>>>(W2h, XZ);

    // Heads: mean = H2@Wm + bm ; cov = softplus(H2@Wc + bc)
    gemm_bf16_hl<0><<<dim3(DOUT_/64, BT_/128), 256>>>(Hh, Hl, wmh, wml, bm, out,
                                                      BT_, DOUT_, H_, DOUT_);
    gemm_bf16_hl<1><<<dim3(DOUT_/64, BT_/128), 256>>>(Hh, Hl, wch, wcl, bc, out + half,
                                                      BT_, DOUT_, H_, DOUT_);
}

// round 12
// speedup vs baseline: 1.1356x; 1.1356x over previous
#include <cuda_runtime.h>
#include <cuda_bf16.h>
#include <math.h>
#include <stdint.h>

#define B_    32
#define T_    1024
#define H_    1024
#define FH_   4096
#define DIN_  256
#define DOUT_ 512
#define BT_   (B_*T_)
#define NBLK_ 128
#define NTH_R 256

// -------- scratch (static device globals; no allocation anywhere) ----------
__device__ float g_XZ[(size_t)BT_*FH_];        // 512 MB, xz for current layer
__device__ __nv_bfloat16 g_Hh[(size_t)BT_*H_]; // layer output hi (reused L1 then L2)
__device__ __nv_bfloat16 g_Hl[(size_t)BT_*H_]; // layer output lo
__device__ __nv_bfloat16 g_hA[2][64*1024];     // step mirror: rows 0-31 h_hi, 32-63 h_lo
// converted operands
__device__ __nv_bfloat16 g_obs_h[(size_t)BT_*DIN_], g_obs_l[(size_t)BT_*DIN_];
__device__ __nv_bfloat16 g_W1x_h[(size_t)DIN_*FH_], g_W1x_l[(size_t)DIN_*FH_];
__device__ __nv_bfloat16 g_W2x_h[(size_t)H_*FH_],   g_W2x_l[(size_t)H_*FH_];
__device__ __nv_bfloat16 g_Wm_h[(size_t)H_*DOUT_],  g_Wm_l[(size_t)H_*DOUT_];
__device__ __nv_bfloat16 g_Wc_h[(size_t)H_*DOUT_],  g_Wc_l[(size_t)H_*DOUT_];

// producer/consumer phase flags: flag[g] = monotonic arrival count of block
// group g (blocks 32g..32g+31, producing h units [256g, 256g+256)).
__device__ unsigned g_flag[4];

__global__ void zero_flags()
{
    if (threadIdx.x < 4) g_flag[threadIdx.x] = 0;
}

__device__ __forceinline__ unsigned ld_acq(const unsigned* p)
{
    unsigned v;
    asm volatile("ld.acquire.gpu.u32 %0, [%1];" : "=r"(v) : "l"(p) : "memory");
    return v;
}
__device__ __forceinline__ void red_rel_add(unsigned* p, unsigned v)
{
    asm volatile("red.release.gpu.add.u32 [%0], %1;" :: "l"(p), "r"(v) : "memory");
}
__device__ __forceinline__ void wait_flag(const unsigned* p, unsigned target)
{
    while (ld_acq(p) < target) { }
}

// ---- cp.async helpers -----------------------------------------------------
__device__ __forceinline__ void cp_async16(void* sptr, const void* gptr)
{
    unsigned sa = (unsigned)__cvta_generic_to_shared(sptr);
    asm volatile("cp.async.cg.shared.global [%0], [%1], 16;" :: "r"(sa), "l"(gptr));
}
__device__ __forceinline__ void cp_commit()
{
    asm volatile("cp.async.commit_group;" ::: "memory");
}
template<int N> __device__ __forceinline__ void cp_wait()
{
    asm volatile("cp.async.wait_group %0;" :: "n"(N) : "memory");
}

// ---- warp-MMA helpers -----------------------------------------------------
__device__ __forceinline__ uint32_t smem_u32(const void* p)
{
    uint32_t a;
    asm("{ .reg .u64 t; cvta.to.shared.u64 t, %1; cvt.u32.u64 %0, t; }" : "=r"(a) : "l"(p));
    return a;
}
__device__ __forceinline__ void ldsm_x4(uint32_t& r0, uint32_t& r1, uint32_t& r2, uint32_t& r3,
                                        uint32_t addr)
{
    asm volatile("ldmatrix.sync.aligned.m8n8.x4.shared.b16 {%0,%1,%2,%3}, [%4];"
                 : "=r"(r0), "=r"(r1), "=r"(r2), "=r"(r3) : "r"(addr));
}
__device__ __forceinline__ void ldsm_x4t(uint32_t& r0, uint32_t& r1, uint32_t& r2, uint32_t& r3,
                                         uint32_t addr)
{
    asm volatile("ldmatrix.sync.aligned.m8n8.x4.trans.shared.b16 {%0,%1,%2,%3}, [%4];"
                 : "=r"(r0), "=r"(r1), "=r"(r2), "=r"(r3) : "r"(addr));
}
__device__ __forceinline__ void mma16816(float* d,
                                         uint32_t a0, uint32_t a1, uint32_t a2, uint32_t a3,
                                         uint32_t b0, uint32_t b1)
{
    asm volatile("mma.sync.aligned.m16n8k16.row.col.f32.bf16.bf16.f32 "
                 "{%0,%1,%2,%3}, {%4,%5,%6,%7}, {%8,%9}, {%0,%1,%2,%3};"
                 : "+f"(d[0]), "+f"(d[1]), "+f"(d[2]), "+f"(d[3])
                 : "r"(a0), "r"(a1), "r"(a2), "r"(a3), "r"(b0), "r"(b1));
}

// recurrence swizzles (validated R9)
#define SW_B(k, nb) ((uint32_t)(k) * 64u + (uint32_t)((((nb) ^ (((k) >> 1) & 3))) * 16))
#define SW_A(m, unit) ((uint32_t)(m) * 512u + (uint32_t)((((unit) ^ ((m) & 7))) * 16))

// ---- recurrence smem layout (bytes) ---------------------------------------
#define SO_WHI   0
#define SO_WLO   65536
#define SO_A     131072          // 2 x 32768
#define SO_Z     196608          // [64][33] f32 = 8448
#define SMEM_R   205056

// ---------------------------------------------------------------------------
// fp32 -> bf16 hi/lo conversion (vectorized by 4)
// ---------------------------------------------------------------------------
__global__ void conv_hl(const float* __restrict__ src, __nv_bfloat16* __restrict__ hi,
                        __nv_bfloat16* __restrict__ lo, int n4)
{
    int i = blockIdx.x * blockDim.x + threadIdx.x;
    if (i < n4) {
        float4 v = ((const float4*)src)[i];
        __nv_bfloat16 h[4], l[4];
        float vv[4] = {v.x, v.y, v.z, v.w};
        #pragma unroll
        for (int j = 0; j < 4; j++) {
            h[j] = __float2bfloat16(vv[j]);
            l[j] = __float2bfloat16(vv[j] - __bfloat162float(h[j]));
        }
        ((uint64_t*)hi)[i] = *(uint64_t*)h;
        ((uint64_t*)lo)[i] = *(uint64_t*)l;
    }
}

// ---------------------------------------------------------------------------
// bf16 hi/lo GEMM (unchanged R10): C = (Ahi+Alo)@(Bhi+Blo) + bias, 3-term.
// ---------------------------------------------------------------------------
template<int EPI>
__global__ __launch_bounds__(256, 2)
void gemm_bf16_hl(const __nv_bfloat16* __restrict__ Ahi, const __nv_bfloat16* __restrict__ Alo,
                  const __nv_bfloat16* __restrict__ Bhi, const __nv_bfloat16* __restrict__ Blo,
                  const float* __restrict__ bias, float* __restrict__ C,
                  int M, int N, int K, int ldc)
{
    __shared__ __align__(128) char sm[32768];
    const uint32_t sA = smem_u32(sm);
    const uint32_t sB = sA + 24576;

    const int tid  = threadIdx.x;
    const int wid  = tid >> 5;
    const int lane = tid & 31;
    const int mt   = wid >> 1;
    const int nh   = wid & 1;
    const int bm   = blockIdx.y * 128;
    const int bn   = blockIdx.x * 64;

    const int arow0 = mt * 32 + (lane & 7) + ((lane >> 3) & 1) * 8;
    const int a_u   = lane >> 4;
    const int kr    = lane & 15;
    const int nb0   = nh * 4 + (lane >> 4);
    const int nb1   = nh * 4 + 2 + (lane >> 4);

    float d[2][2][2][4];
    #pragma unroll
    for (int q = 0; q < 2; q++)
        #pragma unroll
        for (int s = 0; s < 2; s++)
            #pragma unroll
            for (int h8 = 0; h8 < 2; h8++)
                #pragma unroll
                for (int e = 0; e < 4; e++) d[q][s][h8][e] = 0.f;

    const int nk = K / 16;

    {
        #pragma unroll
        for (int i = 0; i < 2; i++) {
            int idx = tid + i * 256;
            int hl = idx >> 8, rem = idx & 255;
            int r = rem >> 1, u = rem & 1;
            const __nv_bfloat16* src = (hl ? Alo : Ahi) + (size_t)(bm + r) * K + u * 8;
            cp_async16(sm + hl * 6144 + r * 48 + u * 16, src);
        }
        {
            int hl = tid >> 7, rem = tid & 127;
            int kk = rem >> 3, nb = rem & 7;
            const __nv_bfloat16* src = (hl ? Blo : Bhi) + (size_t)kk * N + bn + nb * 8;
            cp_async16(sm + 24576 + hl * 2048 + kk * 128 + ((nb ^ (kk & 7)) * 16), src);
        }
        cp_commit();
    }

    for (int c = 0; c < nk; c++) {
        const int buf = c & 1;
        cp_wait<0>();
        __syncthreads();

        if (c + 1 < nk) {
            const int k0 = (c + 1) * 16;
            char* base = (char*)sm + ((buf ^ 1) ? 12288 : 0);
            #pragma unroll
            for (int i = 0; i < 2; i++) {
                int idx = tid + i * 256;
                int hl = idx >> 8, rem = idx & 255;
                int r = rem >> 1, u = rem & 1;
                const __nv_bfloat16* src = (hl ? Alo : Ahi) + (size_t)(bm + r) * K + k0 + u * 8;
                cp_async16(base + hl * 6144 + r * 48 + u * 16, src);
            }
            {
                int hl = tid >> 7, rem = tid & 127;
                int kk = rem >> 3, nb = rem & 7;
                const __nv_bfloat16* src = (hl ? Blo : Bhi) + (size_t)(k0 + kk) * N + bn + nb * 8;
                cp_async16((char*)sm + 24576 + ((buf ^ 1) ? 4096 : 0) + hl * 2048
                           + kk * 128 + ((nb ^ (kk & 7)) * 16), src);
            }
            cp_commit();
        }

        const uint32_t aB = sA + buf * 12288;
        const uint32_t bB = sB + buf * 4096;

        uint32_t ah[2][4], al[2][4], bh[2][4], bl[2][4];
        #pragma unroll
        for (int q = 0; q < 2; q++) {
            uint32_t ra = aB + (uint32_t)(arow0 + q * 16) * 48 + a_u * 16;
            ldsm_x4(ah[q][0], ah[q][1], ah[q][2], ah[q][3], ra);
            ldsm_x4(al[q][0], al[q][1], al[q][2], al[q][3], ra + 6144);
        }
        {
            uint32_t r0 = bB + (uint32_t)kr * 128 + ((nb0 ^ (kr & 7)) * 16);
            uint32_t r1 = bB + (uint32_t)kr * 128 + ((nb1 ^ (kr & 7)) * 16);
            ldsm_x4t(bh[0][0], bh[0][1], bh[0][2], bh[0][3], r0);
            ldsm_x4t(bh[1][0], bh[1][1], bh[1][2], bh[1][3], r1);
            ldsm_x4t(bl[0][0], bl[0][1], bl[0][2], bl[0][3], r0 + 2048);
            ldsm_x4t(bl[1][0], bl[1][1], bl[1][2], bl[1][3], r1 + 2048);
        }

        #pragma unroll
        for (int q = 0; q < 2; q++)
            #pragma unroll
            for (int s = 0; s < 2; s++) {
                mma16816(d[q][s][0], ah[q][0], ah[q][1], ah[q][2], ah[q][3], bh[s][0], bh[s][1]);
                mma16816(d[q][s][1], ah[q][0], ah[q][1], ah[q][2], ah[q][3], bh[s][2], bh[s][3]);
                mma16816(d[q][s][0], ah[q][0], ah[q][1], ah[q][2], ah[q][3], bl[s][0], bl[s][1]);
                mma16816(d[q][s][1], ah[q][0], ah[q][1], ah[q][2], ah[q][3], bl[s][2], bl[s][3]);
                mma16816(d[q][s][0], al[q][0], al[q][1], al[q][2], al[q][3], bh[s][0], bh[s][1]);
                mma16816(d[q][s][1], al[q][0], al[q][1], al[q][2], al[q][3], bh[s][2], bh[s][3]);
            }
        __syncthreads();
    }

    #pragma unroll
    for (int q = 0; q < 2; q++) {
        int row = bm + mt * 32 + q * 16 + (lane >> 2);
        #pragma unroll
        for (int s = 0; s < 2; s++) {
            #pragma unroll
            for (int h8 = 0; h8 < 2; h8++) {
                int col = bn + nh * 32 + s * 16 + h8 * 8 + (lane & 3) * 2;
                float b0 = bias[col], b1 = bias[col + 1];
                float v0 = d[q][s][h8][0] + b0;
                float v1 = d[q][s][h8][1] + b1;
                float v2 = d[q][s][h8][2] + b0;
                float v3 = d[q][s][h8][3] + b1;
                if (EPI == 1) {
                    v0 = (v0 > 20.f) ? v0 : log1pf(expf(v0));
                    v1 = (v1 > 20.f) ? v1 : log1pf(expf(v1));
                    v2 = (v2 > 20.f) ? v2 : log1pf(expf(v2));
                    v3 = (v3 > 20.f) ? v3 : log1pf(expf(v3));
                }
                *(float2*)&C[(size_t)row * ldc + col]       = make_float2(v0, v1);
                *(float2*)&C[(size_t)(row + 8) * ldc + col] = make_float2(v2, v3);
            }
        }
    }
}

// ---------------------------------------------------------------------------
// Persistent warp-MMA LSTM layer (R10 core + phase-flag sync instead of a
// monolithic grid barrier). 128 blocks x 256 threads; block owns 8 units.
// Sync: block arrives on g_flag[bid>>5] (release) after writing h_t; before
// staging phase p of step t it waits g_flag[p] >= 32*t (acquire). Early
// phases' MMA overlaps late groups' arrival.
// ---------------------------------------------------------------------------
__global__ __launch_bounds__(NTH_R, 1)
void lstm_layer_mma(const float* __restrict__ Wh,   // [H, 4H]
                    const float* __restrict__ XZ)   // [B*T, 4H] (bias folded)
{
    extern __shared__ __align__(128) char smem[];
    const uint32_t sbase = smem_u32(smem);
    const uint32_t sWHI  = sbase + SO_WHI;
    const uint32_t sWLO  = sbase + SO_WLO;
    const uint32_t sA    = sbase + SO_A;
    float* zb = (float*)(smem + SO_Z);    // [64][33]

    const int tid  = threadIdx.x;
    const int wid  = tid >> 5;
    const int lane = tid & 31;
    const int u0   = blockIdx.x * 8;
    const int grp  = blockIdx.x >> 5;     // my producer group

    // epilogue identity
    const int eb = tid >> 3;      // batch row 0..31
    const int ej = tid & 7;       // unit index 0..7
    const size_t hrow = (size_t)eb * T_;

    // ---- one-time: W slice -> bf16 hi/lo, swizzled. col(n) = (n>>3)*H + u0 + (n&7)
    for (int idx = tid; idx < 32 * 1024; idx += NTH_R) {
        int n = idx & 31, k = idx >> 5;
        int gcol = (n >> 3) * H_ + u0 + (n & 7);
        float w = Wh[(size_t)k * FH_ + gcol];
        __nv_bfloat16 hi = __float2bfloat16(w);
        __nv_bfloat16 lo = __float2bfloat16(w - __bfloat162float(hi));
        uint32_t off = SW_B(k, n >> 3) + (uint32_t)(n & 7) * 2;
        *(__nv_bfloat16*)(smem + SO_WHI + off) = hi;
        *(__nv_bfloat16*)(smem + SO_WLO + off) = lo;
    }

    float c_reg = 0.f;

    // =========================== t = 0 (h0 = 0) ============================
    {
        const float* xzp = XZ + hrow * FH_ + u0 + ej;
        float zi = __ldg(&xzp[0]);
        float zg = __ldg(&xzp[2 * H_]);
        float zo = __ldg(&xzp[3 * H_]);
        float iv = 1.f / (1.f + __expf(-zi));
        float eg = __expf(-2.f * zg); float gv = (1.f - eg) / (1.f + eg);
        float ov = 1.f / (1.f + __expf(-zo));
        c_reg = iv * gv;
        float ec = __expf(-2.f * c_reg); float tc = (1.f - ec) / (1.f + ec);
        float hv = ov * tc;
        __nv_bfloat16 hi = __float2bfloat16(hv);
        __nv_bfloat16 lo = __float2bfloat16(hv - __bfloat162float(hi));
        g_Hh[hrow * H_ + u0 + ej] = hi;
        g_Hl[hrow * H_ + u0 + ej] = lo;
        g_hA[0][(size_t)eb * 1024 + u0 + ej]        = hi;
        g_hA[0][(size_t)(eb + 32) * 1024 + u0 + ej] = lo;
    }
    __syncthreads();
    if (tid == 0) red_rel_add(&g_flag[grp], 1u);   // arrival for step 0

    // warp tiling (validated R9): warp = (m-tile 0-3) x (n-half 0-1)
    const int mt  = wid >> 1;
    const int nh  = wid & 1;
    const int m_loc = mt * 16 + (lane & 7) + ((lane >> 3) & 1) * 8;
    const int krow  = (lane & 7) + ((lane >> 3) & 1) * 8;
    const int nb    = nh * 2 + (lane >> 4);
    const int uoff  = lane >> 4;

    // =========================== main loop =================================
    for (int t = 1; t < T_; t++) {
        const __nv_bfloat16* hA = g_hA[(t - 1) & 1];
        const unsigned target = 32u * (unsigned)t;

        // prefetch xz gate inputs (independent of flags)
        const float* xzp = XZ + (hrow + t) * FH_ + u0 + ej;
        float x_i = __ldg(&xzp[0]);
        float x_f = __ldg(&xzp[H_]);
        float x_g = __ldg(&xzp[2 * H_]);
        float x_o = __ldg(&xzp[3 * H_]);

        // wait for group 0 producers, then stage phase 0 -> buf0
        wait_flag(&g_flag[0], target);
        #pragma unroll
        for (int i = 0; i < 8; i++) {
            int g = tid + i * 256;
            int r = g >> 5, cc = g & 31;
            cp_async16(smem + SO_A + SW_A(r, cc),
                       (const char*)hA + (size_t)r * 2048 + (size_t)cc * 16);
        }
        cp_commit();

        float d0[4] = {0.f, 0.f, 0.f, 0.f};
        float d1[4] = {0.f, 0.f, 0.f, 0.f};

        #pragma unroll 1
        for (int p = 0; p < 4; p++) {
            cp_wait<0>();
            __syncthreads();

            if (p < 3) {   // wait producers of phase p+1, then prefetch it
                wait_flag(&g_flag[p + 1], target);
                const char* src = (const char*)hA + (size_t)(p + 1) * 512;
                char* dstb = smem + SO_A + (size_t)((p + 1) & 1) * 32768;
                #pragma unroll
                for (int i = 0; i < 8; i++) {
                    int g = tid + i * 256;
                    int r = g >> 5, cc = g & 31;
                    cp_async16(dstb + SW_A(r, cc),
                               src + (size_t)r * 2048 + (size_t)cc * 16);
                }
                cp_commit();
            }

            const uint32_t abase = sA + (uint32_t)(p & 1) * 32768u;
            #pragma unroll
            for (int ks = 0; ks < 16; ks++) {
                uint32_t a0, a1, a2, a3, b0, b1, b2, b3;
                ldsm_x4(a0, a1, a2, a3, abase + SW_A(m_loc, ks * 2 + uoff));
                int kk = p * 256 + ks * 16 + krow;
                uint32_t boff = SW_B(kk, nb);
                ldsm_x4t(b0, b1, b2, b3, sWHI + boff);
                mma16816(d0, a0, a1, a2, a3, b0, b1);
                mma16816(d1, a0, a1, a2, a3, b2, b3);
                ldsm_x4t(b0, b1, b2, b3, sWLO + boff);
                mma16816(d0, a0, a1, a2, a3, b0, b1);
                mma16816(d1, a0, a1, a2, a3, b2, b3);
            }
        }

        // ---- d-frags -> zb[64][33]
        {
            int row = mt * 16 + (lane >> 2);
            int col = nh * 16 + (lane & 3) * 2;
            zb[row * 33 + col]           = d0[0];
            zb[row * 33 + col + 1]       = d0[1];
            zb[(row + 8) * 33 + col]     = d0[2];
            zb[(row + 8) * 33 + col + 1] = d0[3];
            zb[row * 33 + col + 8]           = d1[0];
            zb[row * 33 + col + 9]           = d1[1];
            zb[(row + 8) * 33 + col + 8]     = d1[2];
            zb[(row + 8) * 33 + col + 9]     = d1[3];
        }
        __syncthreads();

        // ---- gates: all 256 threads, one (b, u) each
        {
            float zi = zb[eb * 33 + ej]        + zb[(eb + 32) * 33 + ej]        + x_i;
            float zf = zb[eb * 33 + 8 + ej]    + zb[(eb + 32) * 33 + 8 + ej]    + x_f;
            float zg = zb[eb * 33 + 16 + ej]   + zb[(eb + 32) * 33 + 16 + ej]   + x_g;
            float zo = zb[eb * 33 + 24 + ej]   + zb[(eb + 32) * 33 + 24 + ej]   + x_o;

            float iv = 1.f / (1.f + __expf(-zi));
            float fv = 1.f / (1.f + __expf(-zf));
            float eg = __expf(-2.f * zg); float gv = (1.f - eg) / (1.f + eg);
            float ov = 1.f / (1.f + __expf(-zo));
            c_reg = fv * c_reg + iv * gv;
            float ec = __expf(-2.f * c_reg); float tc = (1.f - ec) / (1.f + ec);
            float hv = ov * tc;

            __nv_bfloat16 hi = __float2bfloat16(hv);
            __nv_bfloat16 lo = __float2bfloat16(hv - __bfloat162float(hi));
            g_Hh[(hrow + t) * H_ + u0 + ej] = hi;
            g_Hl[(hrow + t) * H_ + u0 + ej] = lo;
            g_hA[t & 1][(size_t)eb * 1024 + u0 + ej]        = hi;
            g_hA[t & 1][(size_t)(eb + 32) * 1024 + u0 + ej] = lo;
        }

        __syncthreads();
        if (tid == 0) red_rel_add(&g_flag[grp], 1u);   // arrival for step t
    }
}

// ---------------------------------------------------------------------------
extern "C" void kernel_launch(void* const* d_in, const int* in_sizes, int n_in,
                              void* d_out, int out_size)
{
    const float* obs = (const float*)d_in[0];
    const float* W1x = (const float*)d_in[1];
    const float* W1h = (const float*)d_in[2];
    const float* b1  = (const float*)d_in[3];
    const float* W2x = (const float*)d_in[4];
    const float* W2h = (const float*)d_in[5];
    const float* b2  = (const float*)d_in[6];
    const float* Wm  = (const float*)d_in[7];
    const float* bm  = (const float*)d_in[8];
    const float* Wc  = (const float*)d_in[9];
    const float* bc  = (const float*)d_in[10];

    float* XZ;
    __nv_bfloat16 *Hh, *Hl, *obsh, *obsl, *w1xh, *w1xl, *w2xh, *w2xl, *wmh, *wml, *wch, *wcl;
    cudaGetSymbolAddress((void**)&XZ,   g_XZ);
    cudaGetSymbolAddress((void**)&Hh,   g_Hh);
    cudaGetSymbolAddress((void**)&Hl,   g_Hl);
    cudaGetSymbolAddress((void**)&obsh, g_obs_h);
    cudaGetSymbolAddress((void**)&obsl, g_obs_l);
    cudaGetSymbolAddress((void**)&w1xh, g_W1x_h);
    cudaGetSymbolAddress((void**)&w1xl, g_W1x_l);
    cudaGetSymbolAddress((void**)&w2xh, g_W2x_h);
    cudaGetSymbolAddress((void**)&w2xl, g_W2x_l);
    cudaGetSymbolAddress((void**)&wmh,  g_Wm_h);
    cudaGetSymbolAddress((void**)&wml,  g_Wm_l);
    cudaGetSymbolAddress((void**)&wch,  g_Wc_h);
    cudaGetSymbolAddress((void**)&wcl,  g_Wc_l);

    float* out = (float*)d_out;
    size_t half = (size_t)out_size / 2;   // mean | cov

    cudaFuncSetAttribute(lstm_layer_mma,
                         cudaFuncAttributeMaxDynamicSharedMemorySize, SMEM_R);

    // ---- conversions (fp32 -> bf16 hi/lo)
    conv_hl<<<(BT_*DIN_/4 + 255)/256, 256>>>(obs, obsh, obsl, BT_*DIN_/4);
    conv_hl<<<(DIN_*FH_/4 + 255)/256, 256>>>(W1x, w1xh, w1xl, DIN_*FH_/4);
    conv_hl<<<(H_*FH_/4   + 255)/256, 256>>>(W2x, w2xh, w2xl, H_*FH_/4);
    conv_hl<<<(H_*DOUT_/4 + 255)/256, 256>>>(Wm,  wmh,  wml,  H_*DOUT_/4);
    conv_hl<<<(H_*DOUT_/4 + 255)/256, 256>>>(Wc,  wch,  wcl,  H_*DOUT_/4);

    // XZ1 = obs @ W1x + b1
    gemm_bf16_hl<0><<<dim3(FH_/64, BT_/128), 256>>>(obsh, obsl, w1xh, w1xl, b1, XZ,
                                                    BT_, FH_, DIN_, FH_);

    // Layer 1 recurrence -> g_Hh/g_Hl = H1
    zero_flags<<<1, 32>>>();
    lstm_layer_mma<<<NBLK_, NTH_R, SMEM_R>>>(W1h, XZ);

    // XZ2 = H1 @ W2x + b2
    gemm_bf16_hl<0><<<dim3(FH_/64, BT_/128), 256>>>(Hh, Hl, w2xh, w2xl, b2, XZ,
                                                    BT_, FH_, H_, FH_);

    // Layer 2 recurrence -> g_Hh/g_Hl = H2
    zero_flags<<<1, 32>>>();
    lstm_layer_mma<<<NBLK_, NTH_R, SMEM_R>>>(W2h, XZ);

    // Heads: mean = H2@Wm + bm ; cov = softplus(H2@Wc + bc)
    gemm_bf16_hl<0><<<dim3(DOUT_/64, BT_/128), 256>>>(Hh, Hl, wmh, wml, bm, out,
                                                      BT_, DOUT_, H_, DOUT_);
    gemm_bf16_hl<1><<<dim3(DOUT_/64, BT_/128), 256>>>(Hh, Hl, wch, wcl, bc, out + half,
                                                      BT_, DOUT_, H_, DOUT_);
}

// round 14
// speedup vs baseline: 1.4338x; 1.2626x over previous
#include <cuda_runtime.h>
#include <cuda_bf16.h>
#include <cuda_fp16.h>
#include <math.h>
#include <stdint.h>

#define B_    32
#define T_    1024
#define H_    1024
#define FH_   4096
#define DIN_  256
#define DOUT_ 512
#define BT_   (B_*T_)
#define NBLK_ 128
#define NTH_R 256

// -------- scratch (static device globals; no allocation anywhere) ----------
__device__ float g_XZ[(size_t)BT_*FH_];        // 512 MB, xz for current layer
__device__ __nv_bfloat16 g_Hh[(size_t)BT_*H_]; // layer output hi (for downstream GEMMs)
__device__ __nv_bfloat16 g_Hl[(size_t)BT_*H_]; // layer output lo
__device__ __half g_hA16[2][32*1024];          // step mirror: h as fp16, [b][u]
// converted operands
__device__ __nv_bfloat16 g_obs_h[(size_t)BT_*DIN_], g_obs_l[(size_t)BT_*DIN_];
__device__ __nv_bfloat16 g_W1x_h[(size_t)DIN_*FH_], g_W1x_l[(size_t)DIN_*FH_];
__device__ __nv_bfloat16 g_W2x_h[(size_t)H_*FH_],   g_W2x_l[(size_t)H_*FH_];
__device__ __nv_bfloat16 g_Wm_h[(size_t)H_*DOUT_],  g_Wm_l[(size_t)H_*DOUT_];
__device__ __nv_bfloat16 g_Wc_h[(size_t)H_*DOUT_],  g_Wc_l[(size_t)H_*DOUT_];

// producer/consumer phase flags: flag[g] = monotonic arrival count of block
// group g (blocks 32g..32g+31, producing h units [256g, 256g+256)).
__device__ unsigned g_flag[4];

__global__ void zero_flags()
{
    if (threadIdx.x < 4) g_flag[threadIdx.x] = 0;
}

__device__ __forceinline__ unsigned ld_acq(const unsigned* p)
{
    unsigned v;
    asm volatile("ld.acquire.gpu.u32 %0, [%1];" : "=r"(v) : "l"(p) : "memory");
    return v;
}
__device__ __forceinline__ void red_rel_add(unsigned* p, unsigned v)
{
    asm volatile("red.release.gpu.add.u32 [%0], %1;" :: "l"(p), "r"(v) : "memory");
}
__device__ __forceinline__ void wait_flag(const unsigned* p, unsigned target)
{
    while (ld_acq(p) < target) { }
}

// ---- cp.async helpers -----------------------------------------------------
__device__ __forceinline__ void cp_async16(void* sptr, const void* gptr)
{
    unsigned sa = (unsigned)__cvta_generic_to_shared(sptr);
    asm volatile("cp.async.cg.shared.global [%0], [%1], 16;" :: "r"(sa), "l"(gptr));
}
__device__ __forceinline__ void cp_commit()
{
    asm volatile("cp.async.commit_group;" ::: "memory");
}
template<int N> __device__ __forceinline__ void cp_wait()
{
    asm volatile("cp.async.wait_group %0;" :: "n"(N) : "memory");
}

// ---- warp-MMA helpers -----------------------------------------------------
__device__ __forceinline__ uint32_t smem_u32(const void* p)
{
    uint32_t a;
    asm("{ .reg .u64 t; cvta.to.shared.u64 t, %1; cvt.u32.u64 %0, t; }" : "=r"(a) : "l"(p));
    return a;
}
__device__ __forceinline__ void ldsm_x4(uint32_t& r0, uint32_t& r1, uint32_t& r2, uint32_t& r3,
                                        uint32_t addr)
{
    asm volatile("ldmatrix.sync.aligned.m8n8.x4.shared.b16 {%0,%1,%2,%3}, [%4];"
                 : "=r"(r0), "=r"(r1), "=r"(r2), "=r"(r3) : "r"(addr));
}
__device__ __forceinline__ void ldsm_x4t(uint32_t& r0, uint32_t& r1, uint32_t& r2, uint32_t& r3,
                                         uint32_t addr)
{
    asm volatile("ldmatrix.sync.aligned.m8n8.x4.trans.shared.b16 {%0,%1,%2,%3}, [%4];"
                 : "=r"(r0), "=r"(r1), "=r"(r2), "=r"(r3) : "r"(addr));
}
__device__ __forceinline__ void mma16816(float* d,
                                         uint32_t a0, uint32_t a1, uint32_t a2, uint32_t a3,
                                         uint32_t b0, uint32_t b1)
{
    asm volatile("mma.sync.aligned.m16n8k16.row.col.f32.bf16.bf16.f32 "
                 "{%0,%1,%2,%3}, {%4,%5,%6,%7}, {%8,%9}, {%0,%1,%2,%3};"
                 : "+f"(d[0]), "+f"(d[1]), "+f"(d[2]), "+f"(d[3])
                 : "r"(a0), "r"(a1), "r"(a2), "r"(a3), "r"(b0), "r"(b1));
}
__device__ __forceinline__ void mma16816h(float* d,
                                          uint32_t a0, uint32_t a1, uint32_t a2, uint32_t a3,
                                          uint32_t b0, uint32_t b1)
{
    asm volatile("mma.sync.aligned.m16n8k16.row.col.f32.f16.f16.f32 "
                 "{%0,%1,%2,%3}, {%4,%5,%6,%7}, {%8,%9}, {%0,%1,%2,%3};"
                 : "+f"(d[0]), "+f"(d[1]), "+f"(d[2]), "+f"(d[3])
                 : "r"(a0), "r"(a1), "r"(a2), "r"(a3), "r"(b0), "r"(b1));
}

// recurrence swizzles (validated R9)
#define SW_B(k, nb) ((uint32_t)(k) * 64u + (uint32_t)((((nb) ^ (((k) >> 1) & 3))) * 16))
#define SW_A(m, unit) ((uint32_t)(m) * 512u + (uint32_t)((((unit) ^ ((m) & 7))) * 16))

// ---- recurrence smem layout (bytes) ---------------------------------------
// W fp16 hi (64KB) | W fp16 lo (64KB) | A 3 x 16KB | zb [2][32][33] f32
#define SO_WHI   0
#define SO_WLO   65536
#define SO_A     131072          // 3 x 16384
#define SO_Z     180224          // [2][32][33] f32 = 8448
#define SMEM_R   188672

// ---------------------------------------------------------------------------
// fp32 -> bf16 hi/lo conversion (vectorized by 4)
// ---------------------------------------------------------------------------
__global__ void conv_hl(const float* __restrict__ src, __nv_bfloat16* __restrict__ hi,
                        __nv_bfloat16* __restrict__ lo, int n4)
{
    int i = blockIdx.x * blockDim.x + threadIdx.x;
    if (i < n4) {
        float4 v = ((const float4*)src)[i];
        __nv_bfloat16 h[4], l[4];
        float vv[4] = {v.x, v.y, v.z, v.w};
        #pragma unroll
        for (int j = 0; j < 4; j++) {
            h[j] = __float2bfloat16(vv[j]);
            l[j] = __float2bfloat16(vv[j] - __bfloat162float(h[j]));
        }
        ((uint64_t*)hi)[i] = *(uint64_t*)h;
        ((uint64_t*)lo)[i] = *(uint64_t*)l;
    }
}

// ---------------------------------------------------------------------------
// bf16 hi/lo GEMM (unchanged R10): C = (Ahi+Alo)@(Bhi+Blo) + bias, 3-term.
// ---------------------------------------------------------------------------
template<int EPI>
__global__ __launch_bounds__(256, 2)
void gemm_bf16_hl(const __nv_bfloat16* __restrict__ Ahi, const __nv_bfloat16* __restrict__ Alo,
                  const __nv_bfloat16* __restrict__ Bhi, const __nv_bfloat16* __restrict__ Blo,
                  const float* __restrict__ bias, float* __restrict__ C,
                  int M, int N, int K, int ldc)
{
    __shared__ __align__(128) char sm[32768];
    const uint32_t sA = smem_u32(sm);
    const uint32_t sB = sA + 24576;

    const int tid  = threadIdx.x;
    const int wid  = tid >> 5;
    const int lane = tid & 31;
    const int mt   = wid >> 1;
    const int nh   = wid & 1;
    const int bm   = blockIdx.y * 128;
    const int bn   = blockIdx.x * 64;

    const int arow0 = mt * 32 + (lane & 7) + ((lane >> 3) & 1) * 8;
    const int a_u   = lane >> 4;
    const int kr    = lane & 15;
    const int nb0   = nh * 4 + (lane >> 4);
    const int nb1   = nh * 4 + 2 + (lane >> 4);

    float d[2][2][2][4];
    #pragma unroll
    for (int q = 0; q < 2; q++)
        #pragma unroll
        for (int s = 0; s < 2; s++)
            #pragma unroll
            for (int h8 = 0; h8 < 2; h8++)
                #pragma unroll
                for (int e = 0; e < 4; e++) d[q][s][h8][e] = 0.f;

    const int nk = K / 16;

    {
        #pragma unroll
        for (int i = 0; i < 2; i++) {
            int idx = tid + i * 256;
            int hl = idx >> 8, rem = idx & 255;
            int r = rem >> 1, u = rem & 1;
            const __nv_bfloat16* src = (hl ? Alo : Ahi) + (size_t)(bm + r) * K + u * 8;
            cp_async16(sm + hl * 6144 + r * 48 + u * 16, src);
        }
        {
            int hl = tid >> 7, rem = tid & 127;
            int kk = rem >> 3, nb = rem & 7;
            const __nv_bfloat16* src = (hl ? Blo : Bhi) + (size_t)kk * N + bn + nb * 8;
            cp_async16(sm + 24576 + hl * 2048 + kk * 128 + ((nb ^ (kk & 7)) * 16), src);
        }
        cp_commit();
    }

    for (int c = 0; c < nk; c++) {
        const int buf = c & 1;
        cp_wait<0>();
        __syncthreads();

        if (c + 1 < nk) {
            const int k0 = (c + 1) * 16;
            char* base = (char*)sm + ((buf ^ 1) ? 12288 : 0);
            #pragma unroll
            for (int i = 0; i < 2; i++) {
                int idx = tid + i * 256;
                int hl = idx >> 8, rem = idx & 255;
                int r = rem >> 1, u = rem & 1;
                const __nv_bfloat16* src = (hl ? Alo : Ahi) + (size_t)(bm + r) * K + k0 + u * 8;
                cp_async16(base + hl * 6144 + r * 48 + u * 16, src);
            }
            {
                int hl = tid >> 7, rem = tid & 127;
                int kk = rem >> 3, nb = rem & 7;
                const __nv_bfloat16* src = (hl ? Blo : Bhi) + (size_t)(k0 + kk) * N + bn + nb * 8;
                cp_async16((char*)sm + 24576 + ((buf ^ 1) ? 4096 : 0) + hl * 2048
                           + kk * 128 + ((nb ^ (kk & 7)) * 16), src);
            }
            cp_commit();
        }

        const uint32_t aB = sA + buf * 12288;
        const uint32_t bB = sB + buf * 4096;

        uint32_t ah[2][4], al[2][4], bh[2][4], bl[2][4];
        #pragma unroll
        for (int q = 0; q < 2; q++) {
            uint32_t ra = aB + (uint32_t)(arow0 + q * 16) * 48 + a_u * 16;
            ldsm_x4(ah[q][0], ah[q][1], ah[q][2], ah[q][3], ra);
            ldsm_x4(al[q][0], al[q][1], al[q][2], al[q][3], ra + 6144);
        }
        {
            uint32_t r0 = bB + (uint32_t)kr * 128 + ((nb0 ^ (kr & 7)) * 16);
            uint32_t r1 = bB + (uint32_t)kr * 128 + ((nb1 ^ (kr & 7)) * 16);
            ldsm_x4t(bh[0][0], bh[0][1], bh[0][2], bh[0][3], r0);
            ldsm_x4t(bh[1][0], bh[1][1], bh[1][2], bh[1][3], r1);
            ldsm_x4t(bl[0][0], bl[0][1], bl[0][2], bl[0][3], r0 + 2048);
            ldsm_x4t(bl[1][0], bl[1][1], bl[1][2], bl[1][3], r1 + 2048);
        }

        #pragma unroll
        for (int q = 0; q < 2; q++)
            #pragma unroll
            for (int s = 0; s < 2; s++) {
                mma16816(d[q][s][0], ah[q][0], ah[q][1], ah[q][2], ah[q][3], bh[s][0], bh[s][1]);
                mma16816(d[q][s][1], ah[q][0], ah[q][1], ah[q][2], ah[q][3], bh[s][2], bh[s][3]);
                mma16816(d[q][s][0], ah[q][0], ah[q][1], ah[q][2], ah[q][3], bl[s][0], bl[s][1]);
                mma16816(d[q][s][1], ah[q][0], ah[q][1], ah[q][2], ah[q][3], bl[s][2], bl[s][3]);
                mma16816(d[q][s][0], al[q][0], al[q][1], al[q][2], al[q][3], bh[s][0], bh[s][1]);
                mma16816(d[q][s][1], al[q][0], al[q][1], al[q][2], al[q][3], bh[s][2], bh[s][3]);
            }
        __syncthreads();
    }

    #pragma unroll
    for (int q = 0; q < 2; q++) {
        int row = bm + mt * 32 + q * 16 + (lane >> 2);
        #pragma unroll
        for (int s = 0; s < 2; s++) {
            #pragma unroll
            for (int h8 = 0; h8 < 2; h8++) {
                int col = bn + nh * 32 + s * 16 + h8 * 8 + (lane & 3) * 2;
                float b0 = bias[col], b1 = bias[col + 1];
                float v0 = d[q][s][h8][0] + b0;
                float v1 = d[q][s][h8][1] + b1;
                float v2 = d[q][s][h8][2] + b0;
                float v3 = d[q][s][h8][3] + b1;
                if (EPI == 1) {
                    v0 = (v0 > 20.f) ? v0 : log1pf(expf(v0));
                    v1 = (v1 > 20.f) ? v1 : log1pf(expf(v1));
                    v2 = (v2 > 20.f) ? v2 : log1pf(expf(v2));
                    v3 = (v3 > 20.f) ? v3 : log1pf(expf(v3));
                }
                *(float2*)&C[(size_t)row * ldc + col]       = make_float2(v0, v1);
                *(float2*)&C[(size_t)(row + 8) * ldc + col] = make_float2(v2, v3);
            }
        }
    }
}

// ---------------------------------------------------------------------------
// Persistent warp-MMA LSTM layer v6: h as single fp16 (M=32), W as fp16 hi+lo
// (2 B-products, full W precision). 256 threads, 8 warps =
// (kh 0-1) x (mt 0-1) x (nh 0-1). A staged in 4 phases of 256k (16KB each)
// through a 3-buffer, 2-ahead cp.async pipeline. Phase-flag sync (R12).
// ---------------------------------------------------------------------------
__global__ __launch_bounds__(NTH_R, 1)
void lstm_layer_mma(const float* __restrict__ Wh,   // [H, 4H]
                    const float* __restrict__ XZ)   // [B*T, 4H] (bias folded)
{
    extern __shared__ __align__(128) char smem[];
    const uint32_t sbase = smem_u32(smem);
    const uint32_t sWHI  = sbase + SO_WHI;
    const uint32_t sWLO  = sbase + SO_WLO;
    const uint32_t sA    = sbase + SO_A;
    float* zb = (float*)(smem + SO_Z);    // [2][32][33]

    const int tid  = threadIdx.x;
    const int wid  = tid >> 5;
    const int lane = tid & 31;
    const int u0   = blockIdx.x * 8;
    const int grp  = blockIdx.x >> 5;     // my producer group

    // epilogue identity
    const int eb = tid >> 3;      // batch row 0..31
    const int ej = tid & 7;       // unit index 0..7
    const size_t hrow = (size_t)eb * T_;

    // ---- one-time: W slice -> fp16 hi/lo, swizzled. col(n) = (n>>3)*H + u0 + (n&7)
    for (int idx = tid; idx < 32 * 1024; idx += NTH_R) {
        int n = idx & 31, k = idx >> 5;
        int gcol = (n >> 3) * H_ + u0 + (n & 7);
        float w = Wh[(size_t)k * FH_ + gcol];
        __half hi = __float2half_rn(w);
        __half lo = __float2half_rn(w - __half2float(hi));
        uint32_t off = SW_B(k, n >> 3) + (uint32_t)(n & 7) * 2;
        *(__half*)(smem + SO_WHI + off) = hi;
        *(__half*)(smem + SO_WLO + off) = lo;
    }

    float c_reg = 0.f;

    // =========================== t = 0 (h0 = 0) ============================
    {
        const float* xzp = XZ + hrow * FH_ + u0 + ej;
        float zi = __ldg(&xzp[0]);
        float zg = __ldg(&xzp[2 * H_]);
        float zo = __ldg(&xzp[3 * H_]);
        float iv = 1.f / (1.f + __expf(-zi));
        float eg = __expf(-2.f * zg); float gv = (1.f - eg) / (1.f + eg);
        float ov = 1.f / (1.f + __expf(-zo));
        c_reg = iv * gv;
        float ec = __expf(-2.f * c_reg); float tc = (1.f - ec) / (1.f + ec);
        float hv = ov * tc;
        __nv_bfloat16 hb = __float2bfloat16(hv);
        g_Hh[hrow * H_ + u0 + ej] = hb;
        g_Hl[hrow * H_ + u0 + ej] = __float2bfloat16(hv - __bfloat162float(hb));
        g_hA16[0][(size_t)eb * 1024 + u0 + ej] = __float2half_rn(hv);
    }
    __syncthreads();
    if (tid == 0) red_rel_add(&g_flag[grp], 1u);   // arrival for step 0

    // warp tiling: warp = (kh 0-1, mt 0-1, nh 0-1)
    const int kh  = wid >> 2;
    const int wr  = wid & 3;
    const int mt  = wr >> 1;
    const int nh  = wr & 1;
    const int m_loc = mt * 16 + (lane & 7) + ((lane >> 3) & 1) * 8;  // 0..31
    const int krow  = (lane & 7) + ((lane >> 3) & 1) * 8;
    const int nb    = nh * 2 + (lane >> 4);
    const int uoff  = lane >> 4;
    float* zbk = zb + kh * (32 * 33);

    // =========================== main loop =================================
    for (int t = 1; t < T_; t++) {
        const __half* hA = g_hA16[(t - 1) & 1];
        const unsigned target = 32u * (unsigned)t;

        // prefetch xz gate inputs (independent of flags)
        const float* xzp = XZ + (hrow + t) * FH_ + u0 + ej;
        float x_i = __ldg(&xzp[0]);
        float x_f = __ldg(&xzp[H_]);
        float x_g = __ldg(&xzp[2 * H_]);
        float x_o = __ldg(&xzp[3 * H_]);

        // prologue: stage phases 0 and 1 (16KB each = 4 chunks/thread)
        wait_flag(&g_flag[0], target);
        #pragma unroll
        for (int i = 0; i < 4; i++) {
            int g = tid + i * 256;
            int r = g >> 5, cc = g & 31;
            cp_async16(smem + SO_A + SW_A(r, cc),
                       (const char*)hA + (size_t)r * 2048 + (size_t)cc * 16);
        }
        cp_commit();
        wait_flag(&g_flag[1], target);
        #pragma unroll
        for (int i = 0; i < 4; i++) {
            int g = tid + i * 256;
            int r = g >> 5, cc = g & 31;
            cp_async16(smem + SO_A + 16384 + SW_A(r, cc),
                       (const char*)hA + 512 + (size_t)r * 2048 + (size_t)cc * 16);
        }
        cp_commit();

        float d0[4] = {0.f, 0.f, 0.f, 0.f};
        float d1[4] = {0.f, 0.f, 0.f, 0.f};

        #pragma unroll 1
        for (int p = 0; p < 4; p++) {
            if (p < 3) cp_wait<1>(); else cp_wait<0>();
            __syncthreads();

            if (p < 2) {   // stage phase p+2 into buffer (p+2)%3
                wait_flag(&g_flag[p + 2], target);
                const char* src = (const char*)hA + (size_t)(p + 2) * 512;
                char* dstb = smem + SO_A + (size_t)((p + 2) % 3) * 16384;
                #pragma unroll
                for (int i = 0; i < 4; i++) {
                    int g = tid + i * 256;
                    int r = g >> 5, cc = g & 31;
                    cp_async16(dstb + SW_A(r, cc),
                               src + (size_t)r * 2048 + (size_t)cc * 16);
                }
                cp_commit();
            }

            const uint32_t abase = sA + (uint32_t)(p % 3) * 16384u;
            #pragma unroll
            for (int ks = 0; ks < 8; ks++) {
                const int ksg = kh * 8 + ks;              // k16 slice 0..15
                uint32_t a0, a1, a2, a3, b0, b1, b2, b3;
                ldsm_x4(a0, a1, a2, a3, abase + SW_A(m_loc, ksg * 2 + uoff));
                int kk = p * 256 + ksg * 16 + krow;
                uint32_t boff = SW_B(kk, nb);
                ldsm_x4t(b0, b1, b2, b3, sWHI + boff);
                mma16816h(d0, a0, a1, a2, a3, b0, b1);
                mma16816h(d1, a0, a1, a2, a3, b2, b3);
                ldsm_x4t(b0, b1, b2, b3, sWLO + boff);
                mma16816h(d0, a0, a1, a2, a3, b0, b1);
                mma16816h(d1, a0, a1, a2, a3, b2, b3);
            }
        }

        // ---- d-frags -> zb[kh][32][33]
        {
            int row = mt * 16 + (lane >> 2);
            int col = nh * 16 + (lane & 3) * 2;
            zbk[row * 33 + col]           = d0[0];
            zbk[row * 33 + col + 1]       = d0[1];
            zbk[(row + 8) * 33 + col]     = d0[2];
            zbk[(row + 8) * 33 + col + 1] = d0[3];
            zbk[row * 33 + col + 8]       = d1[0];
            zbk[row * 33 + col + 9]       = d1[1];
            zbk[(row + 8) * 33 + col + 8] = d1[2];
            zbk[(row + 8) * 33 + col + 9] = d1[3];
        }
        __syncthreads();

        // ---- gates: all 256 threads, one (b, u) each; sum the two kh planes
        {
            const int base = eb * 33 + ej;
            float zi = zb[base]      + zb[32 * 33 + base]      + x_i;
            float zf = zb[base + 8]  + zb[32 * 33 + base + 8]  + x_f;
            float zg = zb[base + 16] + zb[32 * 33 + base + 16] + x_g;
            float zo = zb[base + 24] + zb[32 * 33 + base + 24] + x_o;

            float iv = 1.f / (1.f + __expf(-zi));
            float fv = 1.f / (1.f + __expf(-zf));
            float eg = __expf(-2.f * zg); float gv = (1.f - eg) / (1.f + eg);
            float ov = 1.f / (1.f + __expf(-zo));
            c_reg = fv * c_reg + iv * gv;
            float ec = __expf(-2.f * c_reg); float tc = (1.f - ec) / (1.f + ec);
            float hv = ov * tc;

            __nv_bfloat16 hb = __float2bfloat16(hv);
            g_Hh[(hrow + t) * H_ + u0 + ej] = hb;
            g_Hl[(hrow + t) * H_ + u0 + ej] = __float2bfloat16(hv - __bfloat162float(hb));
            g_hA16[t & 1][(size_t)eb * 1024 + u0 + ej] = __float2half_rn(hv);
        }

        __syncthreads();
        if (tid == 0) red_rel_add(&g_flag[grp], 1u);   // arrival for step t
    }
}

// ---------------------------------------------------------------------------
extern "C" void kernel_launch(void* const* d_in, const int* in_sizes, int n_in,
                              void* d_out, int out_size)
{
    const float* obs = (const float*)d_in[0];
    const float* W1x = (const float*)d_in[1];
    const float* W1h = (const float*)d_in[2];
    const float* b1  = (const float*)d_in[3];
    const float* W2x = (const float*)d_in[4];
    const float* W2h = (const float*)d_in[5];
    const float* b2  = (const float*)d_in[6];
    const float* Wm  = (const float*)d_in[7];
    const float* bm  = (const float*)d_in[8];
    const float* Wc  = (const float*)d_in[9];
    const float* bc  = (const float*)d_in[10];

    float* XZ;
    __nv_bfloat16 *Hh, *Hl, *obsh, *obsl, *w1xh, *w1xl, *w2xh, *w2xl, *wmh, *wml, *wch, *wcl;
    cudaGetSymbolAddress((void**)&XZ,   g_XZ);
    cudaGetSymbolAddress((void**)&Hh,   g_Hh);
    cudaGetSymbolAddress((void**)&Hl,   g_Hl);
    cudaGetSymbolAddress((void**)&obsh, g_obs_h);
    cudaGetSymbolAddress((void**)&obsl, g_obs_l);
    cudaGetSymbolAddress((void**)&w1xh, g_W1x_h);
    cudaGetSymbolAddress((void**)&w1xl, g_W1x_l);
    cudaGetSymbolAddress((void**)&w2xh, g_W2x_h);
    cudaGetSymbolAddress((void**)&w2xl, g_W2x_l);
    cudaGetSymbolAddress((void**)&wmh,  g_Wm_h);
    cudaGetSymbolAddress((void**)&wml,  g_Wm_l);
    cudaGetSymbolAddress((void**)&wch,  g_Wc_h);
    cudaGetSymbolAddress((void**)&wcl,  g_Wc_l);

    float* out = (float*)d_out;
    size_t half = (size_t)out_size / 2;   // mean | cov

    cudaFuncSetAttribute(lstm_layer_mma,
                         cudaFuncAttributeMaxDynamicSharedMemorySize, SMEM_R);

    // ---- conversions (fp32 -> bf16 hi/lo)
    conv_hl<<<(BT_*DIN_/4 + 255)/256, 256>>>(obs, obsh, obsl, BT_*DIN_/4);
    conv_hl<<<(DIN_*FH_/4 + 255)/256, 256>>>(W1x, w1xh, w1xl, DIN_*FH_/4);
    conv_hl<<<(H_*FH_/4   + 255)/256, 256>>>(W2x, w2xh, w2xl, H_*FH_/4);
    conv_hl<<<(H_*DOUT_/4 + 255)/256, 256>>>(Wm,  wmh,  wml,  H_*DOUT_/4);
    conv_hl<<<(H_*DOUT_/4 + 255)/256, 256>>>(Wc,  wch,  wcl,  H_*DOUT_/4);

    // XZ1 = obs @ W1x + b1
    gemm_bf16_hl<0><<<dim3(FH_/64, BT_/128), 256>>>(obsh, obsl, w1xh, w1xl, b1, XZ,
                                                    BT_, FH_, DIN_, FH_);

    // Layer 1 recurrence -> g_Hh/g_Hl = H1
    zero_flags<<<1, 32>>>();
    lstm_layer_mma<<<NBLK_, NTH_R, SMEM_R>>>(W1h, XZ);

    // XZ2 = H1 @ W2x + b2
    gemm_bf16_hl<0><<<dim3(FH_/64, BT_/128), 256>>>(Hh, Hl, w2xh, w2xl, b2, XZ,
                                                    BT_, FH_, H_, FH_);

    // Layer 2 recurrence -> g_Hh/g_Hl = H2
    zero_flags<<<1, 32>>>();
    lstm_layer_mma<<<NBLK_, NTH_R, SMEM_R>>>(W2h, XZ);

    // Heads: mean = H2@Wm + bm ; cov = softplus(H2@Wc + bc)
    gemm_bf16_hl<0><<<dim3(DOUT_/64, BT_/128), 256>>>(Hh, Hl, wmh, wml, bm, out,
                                                      BT_, DOUT_, H_, DOUT_);
    gemm_bf16_hl<1><<<dim3(DOUT_/64, BT_/128), 256>>>(Hh, Hl, wch, wcl, bc, out + half,
                                                      BT_, DOUT_, H_, DOUT_);
}

// round 15
// speedup vs baseline: 1.7785x; 1.2404x over previous
#include <cuda_runtime.h>
#include <cuda_bf16.h>
#include <cuda_fp16.h>
#include <math.h>
#include <stdint.h>

#define B_    32
#define T_    1024
#define H_    1024
#define FH_   4096
#define DIN_  256
#define DOUT_ 512
#define BT_   (B_*T_)
#define NBLK_ 128
#define NTH_R 256

// -------- scratch (static device globals; no allocation anywhere) ----------
__device__ float g_XZ[(size_t)BT_*FH_];        // 512 MB, xz for current layer
__device__ __half g_H16[(size_t)BT_*H_];       // unified layer output, fp16 [B,T,H]
// converted operands
__device__ __nv_bfloat16 g_obs_h[(size_t)BT_*DIN_], g_obs_l[(size_t)BT_*DIN_];
__device__ __nv_bfloat16 g_W1x_h[(size_t)DIN_*FH_], g_W1x_l[(size_t)DIN_*FH_];
__device__ __half g_W2x_h[(size_t)H_*FH_],   g_W2x_l[(size_t)H_*FH_];
__device__ __half g_Wm_h[(size_t)H_*DOUT_],  g_Wm_l[(size_t)H_*DOUT_];
__device__ __half g_Wc_h[(size_t)H_*DOUT_],  g_Wc_l[(size_t)H_*DOUT_];

// producer/consumer phase flags: flag[g] = monotonic arrival count of block
// group g (blocks 64g..64g+63, producing h units [512g, 512g+512)).
__device__ unsigned g_flag[4];

__global__ void zero_flags()
{
    if (threadIdx.x < 4) g_flag[threadIdx.x] = 0;
}

__device__ __forceinline__ unsigned ld_acq(const unsigned* p)
{
    unsigned v;
    asm volatile("ld.acquire.gpu.u32 %0, [%1];" : "=r"(v) : "l"(p) : "memory");
    return v;
}
__device__ __forceinline__ void red_rel_add(unsigned* p, unsigned v)
{
    asm volatile("red.release.gpu.add.u32 [%0], %1;" :: "l"(p), "r"(v) : "memory");
}
__device__ __forceinline__ void wait_flag(const unsigned* p, unsigned target)
{
    while (ld_acq(p) < target) { }
}

// ---- cp.async helpers -----------------------------------------------------
__device__ __forceinline__ void cp_async16(void* sptr, const void* gptr)
{
    unsigned sa = (unsigned)__cvta_generic_to_shared(sptr);
    asm volatile("cp.async.cg.shared.global [%0], [%1], 16;" :: "r"(sa), "l"(gptr));
}
__device__ __forceinline__ void cp_commit()
{
    asm volatile("cp.async.commit_group;" ::: "memory");
}
template<int N> __device__ __forceinline__ void cp_wait()
{
    asm volatile("cp.async.wait_group %0;" :: "n"(N) : "memory");
}

// ---- warp-MMA helpers -----------------------------------------------------
__device__ __forceinline__ uint32_t smem_u32(const void* p)
{
    uint32_t a;
    asm("{ .reg .u64 t; cvta.to.shared.u64 t, %1; cvt.u32.u64 %0, t; }" : "=r"(a) : "l"(p));
    return a;
}
__device__ __forceinline__ void ldsm_x4(uint32_t& r0, uint32_t& r1, uint32_t& r2, uint32_t& r3,
                                        uint32_t addr)
{
    asm volatile("ldmatrix.sync.aligned.m8n8.x4.shared.b16 {%0,%1,%2,%3}, [%4];"
                 : "=r"(r0), "=r"(r1), "=r"(r2), "=r"(r3) : "r"(addr));
}
__device__ __forceinline__ void ldsm_x4t(uint32_t& r0, uint32_t& r1, uint32_t& r2, uint32_t& r3,
                                         uint32_t addr)
{
    asm volatile("ldmatrix.sync.aligned.m8n8.x4.trans.shared.b16 {%0,%1,%2,%3}, [%4];"
                 : "=r"(r0), "=r"(r1), "=r"(r2), "=r"(r3) : "r"(addr));
}
__device__ __forceinline__ void mma16816(float* d,
                                         uint32_t a0, uint32_t a1, uint32_t a2, uint32_t a3,
                                         uint32_t b0, uint32_t b1)
{
    asm volatile("mma.sync.aligned.m16n8k16.row.col.f32.bf16.bf16.f32 "
                 "{%0,%1,%2,%3}, {%4,%5,%6,%7}, {%8,%9}, {%0,%1,%2,%3};"
                 : "+f"(d[0]), "+f"(d[1]), "+f"(d[2]), "+f"(d[3])
                 : "r"(a0), "r"(a1), "r"(a2), "r"(a3), "r"(b0), "r"(b1));
}
__device__ __forceinline__ void mma16816h(float* d,
                                          uint32_t a0, uint32_t a1, uint32_t a2, uint32_t a3,
                                          uint32_t b0, uint32_t b1)
{
    asm volatile("mma.sync.aligned.m16n8k16.row.col.f32.f16.f16.f32 "
                 "{%0,%1,%2,%3}, {%4,%5,%6,%7}, {%8,%9}, {%0,%1,%2,%3};"
                 : "+f"(d[0]), "+f"(d[1]), "+f"(d[2]), "+f"(d[3])
                 : "r"(a0), "r"(a1), "r"(a2), "r"(a3), "r"(b0), "r"(b1));
}

// swizzles
#define SW_B(k, nb) ((uint32_t)(k) * 64u + (uint32_t)((((nb) ^ (((k) >> 1) & 3))) * 16))
// A phase tile [32 m][64 units of 16B] (1KB rows)
#define SW_A2(m, unit) ((uint32_t)(m) * 1024u + (uint32_t)((((unit) ^ ((m) & 7))) * 16))

// ---- recurrence smem layout (bytes) ---------------------------------------
// W fp16 hi (64KB) | W fp16 lo (64KB) | A 2 x 32KB | zb [2][32][33] f32
#define SO_WHI   0
#define SO_WLO   65536
#define SO_A     131072          // 2 x 32768
#define SO_Z     196608          // [2][32][33] f32 = 8448
#define SMEM_R   205056

// ---------------------------------------------------------------------------
// fp32 -> bf16 hi/lo conversion (vectorized by 4)
// ---------------------------------------------------------------------------
__global__ void conv_hl(const float* __restrict__ src, __nv_bfloat16* __restrict__ hi,
                        __nv_bfloat16* __restrict__ lo, int n4)
{
    int i = blockIdx.x * blockDim.x + threadIdx.x;
    if (i < n4) {
        float4 v = ((const float4*)src)[i];
        __nv_bfloat16 h[4], l[4];
        float vv[4] = {v.x, v.y, v.z, v.w};
        #pragma unroll
        for (int j = 0; j < 4; j++) {
            h[j] = __float2bfloat16(vv[j]);
            l[j] = __float2bfloat16(vv[j] - __bfloat162float(h[j]));
        }
        ((uint64_t*)hi)[i] = *(uint64_t*)h;
        ((uint64_t*)lo)[i] = *(uint64_t*)l;
    }
}

// fp32 -> fp16 hi/lo conversion
__global__ void conv_hl16(const float* __restrict__ src, __half* __restrict__ hi,
                          __half* __restrict__ lo, int n4)
{
    int i = blockIdx.x * blockDim.x + threadIdx.x;
    if (i < n4) {
        float4 v = ((const float4*)src)[i];
        __half h[4], l[4];
        float vv[4] = {v.x, v.y, v.z, v.w};
        #pragma unroll
        for (int j = 0; j < 4; j++) {
            h[j] = __float2half_rn(vv[j]);
            l[j] = __float2half_rn(vv[j] - __half2float(h[j]));
        }
        ((uint64_t*)hi)[i] = *(uint64_t*)h;
        ((uint64_t*)lo)[i] = *(uint64_t*)l;
    }
}

// ---------------------------------------------------------------------------
// bf16 hi/lo GEMM (validated R10): C = (Ahi+Alo)@(Bhi+Blo) + bias, 3-term.
// Used only for XZ1 (obs-based).
// ---------------------------------------------------------------------------
template<int EPI>
__global__ __launch_bounds__(256, 2)
void gemm_bf16_hl(const __nv_bfloat16* __restrict__ Ahi, const __nv_bfloat16* __restrict__ Alo,
                  const __nv_bfloat16* __restrict__ Bhi, const __nv_bfloat16* __restrict__ Blo,
                  const float* __restrict__ bias, float* __restrict__ C,
                  int M, int N, int K, int ldc)
{
    __shared__ __align__(128) char sm[32768];
    const uint32_t sA = smem_u32(sm);
    const uint32_t sB = sA + 24576;

    const int tid  = threadIdx.x;
    const int wid  = tid >> 5;
    const int lane = tid & 31;
    const int mt   = wid >> 1;
    const int nh   = wid & 1;
    const int bm   = blockIdx.y * 128;
    const int bn   = blockIdx.x * 64;

    const int arow0 = mt * 32 + (lane & 7) + ((lane >> 3) & 1) * 8;
    const int a_u   = lane >> 4;
    const int kr    = lane & 15;
    const int nb0   = nh * 4 + (lane >> 4);
    const int nb1   = nh * 4 + 2 + (lane >> 4);

    float d[2][2][2][4];
    #pragma unroll
    for (int q = 0; q < 2; q++)
        #pragma unroll
        for (int s = 0; s < 2; s++)
            #pragma unroll
            for (int h8 = 0; h8 < 2; h8++)
                #pragma unroll
                for (int e = 0; e < 4; e++) d[q][s][h8][e] = 0.f;

    const int nk = K / 16;

    {
        #pragma unroll
        for (int i = 0; i < 2; i++) {
            int idx = tid + i * 256;
            int hl = idx >> 8, rem = idx & 255;
            int r = rem >> 1, u = rem & 1;
            const __nv_bfloat16* src = (hl ? Alo : Ahi) + (size_t)(bm + r) * K + u * 8;
            cp_async16(sm + hl * 6144 + r * 48 + u * 16, src);
        }
        {
            int hl = tid >> 7, rem = tid & 127;
            int kk = rem >> 3, nb = rem & 7;
            const __nv_bfloat16* src = (hl ? Blo : Bhi) + (size_t)kk * N + bn + nb * 8;
            cp_async16(sm + 24576 + hl * 2048 + kk * 128 + ((nb ^ (kk & 7)) * 16), src);
        }
        cp_commit();
    }

    for (int c = 0; c < nk; c++) {
        const int buf = c & 1;
        cp_wait<0>();
        __syncthreads();

        if (c + 1 < nk) {
            const int k0 = (c + 1) * 16;
            char* base = (char*)sm + ((buf ^ 1) ? 12288 : 0);
            #pragma unroll
            for (int i = 0; i < 2; i++) {
                int idx = tid + i * 256;
                int hl = idx >> 8, rem = idx & 255;
                int r = rem >> 1, u = rem & 1;
                const __nv_bfloat16* src = (hl ? Alo : Ahi) + (size_t)(bm + r) * K + k0 + u * 8;
                cp_async16(base + hl * 6144 + r * 48 + u * 16, src);
            }
            {
                int hl = tid >> 7, rem = tid & 127;
                int kk = rem >> 3, nb = rem & 7;
                const __nv_bfloat16* src = (hl ? Blo : Bhi) + (size_t)(k0 + kk) * N + bn + nb * 8;
                cp_async16((char*)sm + 24576 + ((buf ^ 1) ? 4096 : 0) + hl * 2048
                           + kk * 128 + ((nb ^ (kk & 7)) * 16), src);
            }
            cp_commit();
        }

        const uint32_t aB = sA + buf * 12288;
        const uint32_t bB = sB + buf * 4096;

        uint32_t ah[2][4], al[2][4], bh[2][4], bl[2][4];
        #pragma unroll
        for (int q = 0; q < 2; q++) {
            uint32_t ra = aB + (uint32_t)(arow0 + q * 16) * 48 + a_u * 16;
            ldsm_x4(ah[q][0], ah[q][1], ah[q][2], ah[q][3], ra);
            ldsm_x4(al[q][0], al[q][1], al[q][2], al[q][3], ra + 6144);
        }
        {
            uint32_t r0 = bB + (uint32_t)kr * 128 + ((nb0 ^ (kr & 7)) * 16);
            uint32_t r1 = bB + (uint32_t)kr * 128 + ((nb1 ^ (kr & 7)) * 16);
            ldsm_x4t(bh[0][0], bh[0][1], bh[0][2], bh[0][3], r0);
            ldsm_x4t(bh[1][0], bh[1][1], bh[1][2], bh[1][3], r1);
            ldsm_x4t(bl[0][0], bl[0][1], bl[0][2], bl[0][3], r0 + 2048);
            ldsm_x4t(bl[1][0], bl[1][1], bl[1][2], bl[1][3], r1 + 2048);
        }

        #pragma unroll
        for (int q = 0; q < 2; q++)
            #pragma unroll
            for (int s = 0; s < 2; s++) {
                mma16816(d[q][s][0], ah[q][0], ah[q][1], ah[q][2], ah[q][3], bh[s][0], bh[s][1]);
                mma16816(d[q][s][1], ah[q][0], ah[q][1], ah[q][2], ah[q][3], bh[s][2], bh[s][3]);
                mma16816(d[q][s][0], ah[q][0], ah[q][1], ah[q][2], ah[q][3], bl[s][0], bl[s][1]);
                mma16816(d[q][s][1], ah[q][0], ah[q][1], ah[q][2], ah[q][3], bl[s][2], bl[s][3]);
                mma16816(d[q][s][0], al[q][0], al[q][1], al[q][2], al[q][3], bh[s][0], bh[s][1]);
                mma16816(d[q][s][1], al[q][0], al[q][1], al[q][2], al[q][3], bh[s][2], bh[s][3]);
            }
        __syncthreads();
    }

    #pragma unroll
    for (int q = 0; q < 2; q++) {
        int row = bm + mt * 32 + q * 16 + (lane >> 2);
        #pragma unroll
        for (int s = 0; s < 2; s++) {
            #pragma unroll
            for (int h8 = 0; h8 < 2; h8++) {
                int col = bn + nh * 32 + s * 16 + h8 * 8 + (lane & 3) * 2;
                float b0 = bias[col], b1 = bias[col + 1];
                float v0 = d[q][s][h8][0] + b0;
                float v1 = d[q][s][h8][1] + b1;
                float v2 = d[q][s][h8][2] + b0;
                float v3 = d[q][s][h8][3] + b1;
                if (EPI == 1) {
                    v0 = (v0 > 20.f) ? v0 : log1pf(expf(v0));
                    v1 = (v1 > 20.f) ? v1 : log1pf(expf(v1));
                    v2 = (v2 > 20.f) ? v2 : log1pf(expf(v2));
                    v3 = (v3 > 20.f) ? v3 : log1pf(expf(v3));
                }
                *(float2*)&C[(size_t)row * ldc + col]       = make_float2(v0, v1);
                *(float2*)&C[(size_t)(row + 8) * ldc + col] = make_float2(v2, v3);
            }
        }
    }
}

// ---------------------------------------------------------------------------
// fp16 GEMM: C = A @ (Bhi+Blo) + bias.  A single fp16 (the recurrence's own
// quantized h), B fp16 hi/lo (full W precision). 2-term, fp32 accum.
// Block tile 128x64, 256 threads (8 warps = 4 mt x 2 nh), BK=16, dbl-buffered.
// ---------------------------------------------------------------------------
template<int EPI>
__global__ __launch_bounds__(256, 2)
void gemm_f16(const __half* __restrict__ A,
              const __half* __restrict__ Bhi, const __half* __restrict__ Blo,
              const float* __restrict__ bias, float* __restrict__ C,
              int M, int N, int K, int ldc)
{
    // sA: 2 buf x 128 rows x 48B = 12288 ; sB: 2 buf x 2 hl x 2048 = 8192
    __shared__ __align__(128) char sm[20480];
    const uint32_t sA = smem_u32(sm);
    const uint32_t sB = sA + 12288;

    const int tid  = threadIdx.x;
    const int wid  = tid >> 5;
    const int lane = tid & 31;
    const int mt   = wid >> 1;
    const int nh   = wid & 1;
    const int bm   = blockIdx.y * 128;
    const int bn   = blockIdx.x * 64;

    const int arow0 = mt * 32 + (lane & 7) + ((lane >> 3) & 1) * 8;
    const int a_u   = lane >> 4;
    const int kr    = lane & 15;
    const int nb0   = nh * 4 + (lane >> 4);
    const int nb1   = nh * 4 + 2 + (lane >> 4);

    float d[2][2][2][4];
    #pragma unroll
    for (int q = 0; q < 2; q++)
        #pragma unroll
        for (int s = 0; s < 2; s++)
            #pragma unroll
            for (int h8 = 0; h8 < 2; h8++)
                #pragma unroll
                for (int e = 0; e < 4; e++) d[q][s][h8][e] = 0.f;

    const int nk = K / 16;

    {   // prologue: k-tile 0 -> buf 0
        {
            int r = tid >> 1, u = tid & 1;
            cp_async16(sm + r * 48 + u * 16, A + (size_t)(bm + r) * K + u * 8);
        }
        {
            int hl = tid >> 7, rem = tid & 127;
            int kk = rem >> 3, nb = rem & 7;
            const __half* src = (hl ? Blo : Bhi) + (size_t)kk * N + bn + nb * 8;
            cp_async16(sm + 12288 + hl * 2048 + kk * 128 + ((nb ^ (kk & 7)) * 16), src);
        }
        cp_commit();
    }

    for (int c = 0; c < nk; c++) {
        const int buf = c & 1;
        cp_wait<0>();
        __syncthreads();

        if (c + 1 < nk) {
            const int k0 = (c + 1) * 16;
            {
                int r = tid >> 1, u = tid & 1;
                cp_async16((char*)sm + ((buf ^ 1) ? 6144 : 0) + r * 48 + u * 16,
                           A + (size_t)(bm + r) * K + k0 + u * 8);
            }
            {
                int hl = tid >> 7, rem = tid & 127;
                int kk = rem >> 3, nb = rem & 7;
                const __half* src = (hl ? Blo : Bhi) + (size_t)(k0 + kk) * N + bn + nb * 8;
                cp_async16((char*)sm + 12288 + ((buf ^ 1) ? 4096 : 0) + hl * 2048
                           + kk * 128 + ((nb ^ (kk & 7)) * 16), src);
            }
            cp_commit();
        }

        const uint32_t aB = sA + buf * 6144;
        const uint32_t bB = sB + buf * 4096;

        uint32_t ah[2][4], bh[2][4], bl[2][4];
        #pragma unroll
        for (int q = 0; q < 2; q++) {
            uint32_t ra = aB + (uint32_t)(arow0 + q * 16) * 48 + a_u * 16;
            ldsm_x4(ah[q][0], ah[q][1], ah[q][2], ah[q][3], ra);
        }
        {
            uint32_t r0 = bB + (uint32_t)kr * 128 + ((nb0 ^ (kr & 7)) * 16);
            uint32_t r1 = bB + (uint32_t)kr * 128 + ((nb1 ^ (kr & 7)) * 16);
            ldsm_x4t(bh[0][0], bh[0][1], bh[0][2], bh[0][3], r0);
            ldsm_x4t(bh[1][0], bh[1][1], bh[1][2], bh[1][3], r1);
            ldsm_x4t(bl[0][0], bl[0][1], bl[0][2], bl[0][3], r0 + 2048);
            ldsm_x4t(bl[1][0], bl[1][1], bl[1][2], bl[1][3], r1 + 2048);
        }

        #pragma unroll
        for (int q = 0; q < 2; q++)
            #pragma unroll
            for (int s = 0; s < 2; s++) {
                mma16816h(d[q][s][0], ah[q][0], ah[q][1], ah[q][2], ah[q][3], bh[s][0], bh[s][1]);
                mma16816h(d[q][s][1], ah[q][0], ah[q][1], ah[q][2], ah[q][3], bh[s][2], bh[s][3]);
                mma16816h(d[q][s][0], ah[q][0], ah[q][1], ah[q][2], ah[q][3], bl[s][0], bl[s][1]);
                mma16816h(d[q][s][1], ah[q][0], ah[q][1], ah[q][2], ah[q][3], bl[s][2], bl[s][3]);
            }
        __syncthreads();
    }

    #pragma unroll
    for (int q = 0; q < 2; q++) {
        int row = bm + mt * 32 + q * 16 + (lane >> 2);
        #pragma unroll
        for (int s = 0; s < 2; s++) {
            #pragma unroll
            for (int h8 = 0; h8 < 2; h8++) {
                int col = bn + nh * 32 + s * 16 + h8 * 8 + (lane & 3) * 2;
                float b0 = bias[col], b1 = bias[col + 1];
                float v0 = d[q][s][h8][0] + b0;
                float v1 = d[q][s][h8][1] + b1;
                float v2 = d[q][s][h8][2] + b0;
                float v3 = d[q][s][h8][3] + b1;
                if (EPI == 1) {
                    v0 = (v0 > 20.f) ? v0 : log1pf(expf(v0));
                    v1 = (v1 > 20.f) ? v1 : log1pf(expf(v1));
                    v2 = (v2 > 20.f) ? v2 : log1pf(expf(v2));
                    v3 = (v3 > 20.f) ? v3 : log1pf(expf(v3));
                }
                *(float2*)&C[(size_t)row * ldc + col]       = make_float2(v0, v1);
                *(float2*)&C[(size_t)(row + 8) * ldc + col] = make_float2(v2, v3);
            }
        }
    }
}

// ---------------------------------------------------------------------------
// Persistent warp-MMA LSTM layer v7: h fp16 (M=32), W fp16 hi+lo; 2-phase
// (512 k) double-buffered staging straight from unified g_H16[B,T,H].
// 256 threads, 8 warps = (kh 0-1)(mt 0-1)(nh 0-1). 2 flag waits + 4 syncs
// per step. Epilogue writes ONE fp16 array.
// ---------------------------------------------------------------------------
__global__ __launch_bounds__(NTH_R, 1)
void lstm_layer_mma(const float* __restrict__ Wh,   // [H, 4H]
                    const float* __restrict__ XZ)   // [B*T, 4H] (bias folded)
{
    extern __shared__ __align__(128) char smem[];
    const uint32_t sbase = smem_u32(smem);
    const uint32_t sWHI  = sbase + SO_WHI;
    const uint32_t sWLO  = sbase + SO_WLO;
    const uint32_t sA    = sbase + SO_A;
    float* zb = (float*)(smem + SO_Z);    // [2][32][33]

    const int tid  = threadIdx.x;
    const int wid  = tid >> 5;
    const int lane = tid & 31;
    const int u0   = blockIdx.x * 8;
    const int grp  = blockIdx.x >> 6;     // 2 producer groups of 64 blocks

    // epilogue identity
    const int eb = tid >> 3;      // batch row 0..31
    const int ej = tid & 7;       // unit index 0..7
    const size_t hrow = (size_t)eb * T_;

    // ---- one-time: W slice -> fp16 hi/lo, swizzled. col(n) = (n>>3)*H + u0 + (n&7)
    for (int idx = tid; idx < 32 * 1024; idx += NTH_R) {
        int n = idx & 31, k = idx >> 5;
        int gcol = (n >> 3) * H_ + u0 + (n & 7);
        float w = Wh[(size_t)k * FH_ + gcol];
        __half hi = __float2half_rn(w);
        __half lo = __float2half_rn(w - __half2float(hi));
        uint32_t off = SW_B(k, n >> 3) + (uint32_t)(n & 7) * 2;
        *(__half*)(smem + SO_WHI + off) = hi;
        *(__half*)(smem + SO_WLO + off) = lo;
    }

    float c_reg = 0.f;

    // =========================== t = 0 (h0 = 0) ============================
    {
        const float* xzp = XZ + hrow * FH_ + u0 + ej;
        float zi = __ldg(&xzp[0]);
        float zg = __ldg(&xzp[2 * H_]);
        float zo = __ldg(&xzp[3 * H_]);
        float iv = 1.f / (1.f + __expf(-zi));
        float eg = __expf(-2.f * zg); float gv = (1.f - eg) / (1.f + eg);
        float ov = 1.f / (1.f + __expf(-zo));
        c_reg = iv * gv;
        float ec = __expf(-2.f * c_reg); float tc = (1.f - ec) / (1.f + ec);
        float hv = ov * tc;
        g_H16[hrow * H_ + u0 + ej] = __float2half_rn(hv);
    }
    __syncthreads();
    if (tid == 0) red_rel_add(&g_flag[grp], 1u);   // arrival for step 0

    // warp tiling: warp = (kh 0-1, mt 0-1, nh 0-1)
    const int kh  = wid >> 2;
    const int wr  = wid & 3;
    const int mt  = wr >> 1;
    const int nh  = wr & 1;
    const int m_loc = mt * 16 + (lane & 7) + ((lane >> 3) & 1) * 8;  // 0..31
    const int krow  = (lane & 7) + ((lane >> 3) & 1) * 8;
    const int nb    = nh * 2 + (lane >> 4);
    const int uoff  = lane >> 4;
    float* zbk = zb + kh * (32 * 33);

    // =========================== main loop =================================
    for (int t = 1; t < T_; t++) {
        const unsigned target = 64u * (unsigned)t;

        // prefetch xz gate inputs (independent of flags)
        const float* xzp = XZ + (hrow + t) * FH_ + u0 + ej;
        float x_i = __ldg(&xzp[0]);
        float x_f = __ldg(&xzp[H_]);
        float x_g = __ldg(&xzp[2 * H_]);
        float x_o = __ldg(&xzp[3 * H_]);

        // stage phase 0 (units [0,512), produced by group 0) -> buf0
        wait_flag(&g_flag[0], target);
        #pragma unroll
        for (int i = 0; i < 8; i++) {
            int g = tid + i * 256;
            int r = g >> 6, cc = g & 63;
            cp_async16(smem + SO_A + SW_A2(r, cc),
                       (const char*)g_H16
                       + (((size_t)r * T_ + (t - 1)) * H_ + (size_t)cc * 8) * 2);
        }
        cp_commit();
        // stage phase 1 (units [512,1024), produced by group 1) -> buf1
        wait_flag(&g_flag[1], target);
        #pragma unroll
        for (int i = 0; i < 8; i++) {
            int g = tid + i * 256;
            int r = g >> 6, cc = g & 63;
            cp_async16(smem + SO_A + 32768 + SW_A2(r, cc),
                       (const char*)g_H16
                       + (((size_t)r * T_ + (t - 1)) * H_ + 512 + (size_t)cc * 8) * 2);
        }
        cp_commit();

        float d0[4] = {0.f, 0.f, 0.f, 0.f};
        float d1[4] = {0.f, 0.f, 0.f, 0.f};

        #pragma unroll 1
        for (int p = 0; p < 2; p++) {
            if (p == 0) cp_wait<1>(); else cp_wait<0>();
            __syncthreads();

            const uint32_t abase = sA + (uint32_t)p * 32768u;
            #pragma unroll
            for (int ks = 0; ks < 16; ks++) {
                const int ksg = kh * 16 + ks;             // k16 slice 0..31 in phase
                uint32_t a0, a1, a2, a3, b0, b1, b2, b3;
                ldsm_x4(a0, a1, a2, a3, abase + SW_A2(m_loc, ksg * 2 + uoff));
                int kk = p * 512 + ksg * 16 + krow;
                uint32_t boff = SW_B(kk, nb);
                ldsm_x4t(b0, b1, b2, b3, sWHI + boff);
                mma16816h(d0, a0, a1, a2, a3, b0, b1);
                mma16816h(d1, a0, a1, a2, a3, b2, b3);
                ldsm_x4t(b0, b1, b2, b3, sWLO + boff);
                mma16816h(d0, a0, a1, a2, a3, b0, b1);
                mma16816h(d1, a0, a1, a2, a3, b2, b3);
            }
        }

        // ---- d-frags -> zb[kh][32][33]
        {
            int row = mt * 16 + (lane >> 2);
            int col = nh * 16 + (lane & 3) * 2;
            zbk[row * 33 + col]           = d0[0];
            zbk[row * 33 + col + 1]       = d0[1];
            zbk[(row + 8) * 33 + col]     = d0[2];
            zbk[(row + 8) * 33 + col + 1] = d0[3];
            zbk[row * 33 + col + 8]       = d1[0];
            zbk[row * 33 + col + 9]       = d1[1];
            zbk[(row + 8) * 33 + col + 8] = d1[2];
            zbk[(row + 8) * 33 + col + 9] = d1[3];
        }
        __syncthreads();

        // ---- gates: all 256 threads, one (b, u) each; sum the two kh planes
        {
            const int base = eb * 33 + ej;
            float zi = zb[base]      + zb[32 * 33 + base]      + x_i;
            float zf = zb[base + 8]  + zb[32 * 33 + base + 8]  + x_f;
            float zg = zb[base + 16] + zb[32 * 33 + base + 16] + x_g;
            float zo = zb[base + 24] + zb[32 * 33 + base + 24] + x_o;

            float iv = 1.f / (1.f + __expf(-zi));
            float fv = 1.f / (1.f + __expf(-zf));
            float eg = __expf(-2.f * zg); float gv = (1.f - eg) / (1.f + eg);
            float ov = 1.f / (1.f + __expf(-zo));
            c_reg = fv * c_reg + iv * gv;
            float ec = __expf(-2.f * c_reg); float tc = (1.f - ec) / (1.f + ec);
            float hv = ov * tc;

            g_H16[(hrow + t) * H_ + u0 + ej] = __float2half_rn(hv);
        }

        __syncthreads();
        if (tid == 0) red_rel_add(&g_flag[grp], 1u);   // arrival for step t
    }
}

// ---------------------------------------------------------------------------
extern "C" void kernel_launch(void* const* d_in, const int* in_sizes, int n_in,
                              void* d_out, int out_size)
{
    const float* obs = (const float*)d_in[0];
    const float* W1x = (const float*)d_in[1];
    const float* W1h = (const float*)d_in[2];
    const float* b1  = (const float*)d_in[3];
    const float* W2x = (const float*)d_in[4];
    const float* W2h = (const float*)d_in[5];
    const float* b2  = (const float*)d_in[6];
    const float* Wm  = (const float*)d_in[7];
    const float* bm  = (const float*)d_in[8];
    const float* Wc  = (const float*)d_in[9];
    const float* bc  = (const float*)d_in[10];

    float* XZ;
    __half *H16, *w2xh, *w2xl, *wmh, *wml, *wch, *wcl;
    __nv_bfloat16 *obsh, *obsl, *w1xh, *w1xl;
    cudaGetSymbolAddress((void**)&XZ,   g_XZ);
    cudaGetSymbolAddress((void**)&H16,  g_H16);
    cudaGetSymbolAddress((void**)&obsh, g_obs_h);
    cudaGetSymbolAddress((void**)&obsl, g_obs_l);
    cudaGetSymbolAddress((void**)&w1xh, g_W1x_h);
    cudaGetSymbolAddress((void**)&w1xl, g_W1x_l);
    cudaGetSymbolAddress((void**)&w2xh, g_W2x_h);
    cudaGetSymbolAddress((void**)&w2xl, g_W2x_l);
    cudaGetSymbolAddress((void**)&wmh,  g_Wm_h);
    cudaGetSymbolAddress((void**)&wml,  g_Wm_l);
    cudaGetSymbolAddress((void**)&wch,  g_Wc_h);
    cudaGetSymbolAddress((void**)&wcl,  g_Wc_l);

    float* out = (float*)d_out;
    size_t half = (size_t)out_size / 2;   // mean | cov

    cudaFuncSetAttribute(lstm_layer_mma,
                         cudaFuncAttributeMaxDynamicSharedMemorySize, SMEM_R);

    // ---- conversions
    conv_hl  <<<(BT_*DIN_/4 + 255)/256, 256>>>(obs, obsh, obsl, BT_*DIN_/4);
    conv_hl  <<<(DIN_*FH_/4 + 255)/256, 256>>>(W1x, w1xh, w1xl, DIN_*FH_/4);
    conv_hl16<<<(H_*FH_/4   + 255)/256, 256>>>(W2x, w2xh, w2xl, H_*FH_/4);
    conv_hl16<<<(H_*DOUT_/4 + 255)/256, 256>>>(Wm,  wmh,  wml,  H_*DOUT_/4);
    conv_hl16<<<(H_*DOUT_/4 + 255)/256, 256>>>(Wc,  wch,  wcl,  H_*DOUT_/4);

    // XZ1 = obs @ W1x + b1   (bf16 3-term, full input precision)
    gemm_bf16_hl<0><<<dim3(FH_/64, BT_/128), 256>>>(obsh, obsl, w1xh, w1xl, b1, XZ,
                                                    BT_, FH_, DIN_, FH_);

    // Layer 1 recurrence -> g_H16 = H1 (fp16)
    zero_flags<<<1, 32>>>();
    lstm_layer_mma<<<NBLK_, NTH_R, SMEM_R>>>(W1h, XZ);

    // XZ2 = H1 @ W2x + b2   (fp16 A, fp16 hi/lo W)
    gemm_f16<0><<<dim3(FH_/64, BT_/128), 256>>>(H16, w2xh, w2xl, b2, XZ,
                                                BT_, FH_, H_, FH_);

    // Layer 2 recurrence -> g_H16 = H2
    zero_flags<<<1, 32>>>();
    lstm_layer_mma<<<NBLK_, NTH_R, SMEM_R>>>(W2h, XZ);

    // Heads: mean = H2@Wm + bm ; cov = softplus(H2@Wc + bc)
    gemm_f16<0><<<dim3(DOUT_/64, BT_/128), 256>>>(H16, wmh, wml, bm, out,
                                                  BT_, DOUT_, H_, DOUT_);
    gemm_f16<1><<<dim3(DOUT_/64, BT_/128), 256>>>(H16, wch, wcl, bc, out + half,
                                                  BT_, DOUT_, H_, DOUT_);
}

// round 16
// speedup vs baseline: 1.7808x; 1.0013x over previous
#include <cuda_runtime.h>
#include <cuda_bf16.h>
#include <cuda_fp16.h>
#include <math.h>
#include <stdint.h>

#define B_    32
#define T_    1024
#define H_    1024
#define FH_   4096
#define DIN_  256
#define DOUT_ 512
#define BT_   (B_*T_)
#define NBLK_ 128
#define NTH_R 256

// -------- scratch (static device globals; no allocation anywhere) ----------
__device__ float g_XZ[(size_t)BT_*FH_];        // 512 MB, xz for current layer
__device__ __half g_H16[(size_t)BT_*H_];       // unified layer output, fp16 [B,T,H]
// converted operands
__device__ __nv_bfloat16 g_obs_h[(size_t)BT_*DIN_], g_obs_l[(size_t)BT_*DIN_];
__device__ __nv_bfloat16 g_W1x_h[(size_t)DIN_*FH_], g_W1x_l[(size_t)DIN_*FH_];
__device__ __half g_W2x_h[(size_t)H_*FH_],   g_W2x_l[(size_t)H_*FH_];
__device__ __half g_Wm_h[(size_t)H_*DOUT_],  g_Wm_l[(size_t)H_*DOUT_];
__device__ __half g_Wc_h[(size_t)H_*DOUT_],  g_Wc_l[(size_t)H_*DOUT_];

// producer/consumer phase flags: flag[g] = monotonic arrival count of block
// group g (blocks 64g..64g+63, producing h units [512g, 512g+512)).
__device__ unsigned g_flag[4];

__global__ void zero_flags()
{
    if (threadIdx.x < 4) g_flag[threadIdx.x] = 0;
}

__device__ __forceinline__ unsigned ld_acq(const unsigned* p)
{
    unsigned v;
    asm volatile("ld.acquire.gpu.u32 %0, [%1];" : "=r"(v) : "l"(p) : "memory");
    return v;
}
__device__ __forceinline__ void red_rel_add(unsigned* p, unsigned v)
{
    asm volatile("red.release.gpu.add.u32 [%0], %1;" :: "l"(p), "r"(v) : "memory");
}
__device__ __forceinline__ void wait_flag(const unsigned* p, unsigned target)
{
    while (ld_acq(p) < target) { }
}

// ---- cp.async helpers -----------------------------------------------------
__device__ __forceinline__ void cp_async16(void* sptr, const void* gptr)
{
    unsigned sa = (unsigned)__cvta_generic_to_shared(sptr);
    asm volatile("cp.async.cg.shared.global [%0], [%1], 16;" :: "r"(sa), "l"(gptr));
}
__device__ __forceinline__ void cp_commit()
{
    asm volatile("cp.async.commit_group;" ::: "memory");
}
template<int N> __device__ __forceinline__ void cp_wait()
{
    asm volatile("cp.async.wait_group %0;" :: "n"(N) : "memory");
}

// ---- warp-MMA helpers -----------------------------------------------------
__device__ __forceinline__ uint32_t smem_u32(const void* p)
{
    uint32_t a;
    asm("{ .reg .u64 t; cvta.to.shared.u64 t, %1; cvt.u32.u64 %0, t; }" : "=r"(a) : "l"(p));
    return a;
}
__device__ __forceinline__ void ldsm_x4(uint32_t& r0, uint32_t& r1, uint32_t& r2, uint32_t& r3,
                                        uint32_t addr)
{
    asm volatile("ldmatrix.sync.aligned.m8n8.x4.shared.b16 {%0,%1,%2,%3}, [%4];"
                 : "=r"(r0), "=r"(r1), "=r"(r2), "=r"(r3) : "r"(addr));
}
__device__ __forceinline__ void ldsm_x4t(uint32_t& r0, uint32_t& r1, uint32_t& r2, uint32_t& r3,
                                         uint32_t addr)
{
    asm volatile("ldmatrix.sync.aligned.m8n8.x4.trans.shared.b16 {%0,%1,%2,%3}, [%4];"
                 : "=r"(r0), "=r"(r1), "=r"(r2), "=r"(r3) : "r"(addr));
}
__device__ __forceinline__ void mma16816(float* d,
                                         uint32_t a0, uint32_t a1, uint32_t a2, uint32_t a3,
                                         uint32_t b0, uint32_t b1)
{
    asm volatile("mma.sync.aligned.m16n8k16.row.col.f32.bf16.bf16.f32 "
                 "{%0,%1,%2,%3}, {%4,%5,%6,%7}, {%8,%9}, {%0,%1,%2,%3};"
                 : "+f"(d[0]), "+f"(d[1]), "+f"(d[2]), "+f"(d[3])
                 : "r"(a0), "r"(a1), "r"(a2), "r"(a3), "r"(b0), "r"(b1));
}
__device__ __forceinline__ void mma16816h(float* d,
                                          uint32_t a0, uint32_t a1, uint32_t a2, uint32_t a3,
                                          uint32_t b0, uint32_t b1)
{
    asm volatile("mma.sync.aligned.m16n8k16.row.col.f32.f16.f16.f32 "
                 "{%0,%1,%2,%3}, {%4,%5,%6,%7}, {%8,%9}, {%0,%1,%2,%3};"
                 : "+f"(d[0]), "+f"(d[1]), "+f"(d[2]), "+f"(d[3])
                 : "r"(a0), "r"(a1), "r"(a2), "r"(a3), "r"(b0), "r"(b1));
}

// swizzles
#define SW_B(k, nb) ((uint32_t)(k) * 64u + (uint32_t)((((nb) ^ (((k) >> 1) & 3))) * 16))
// A phase tile [32 m][64 units of 16B] (1KB rows)
#define SW_A2(m, unit) ((uint32_t)(m) * 1024u + (uint32_t)((((unit) ^ ((m) & 7))) * 16))

// ---- recurrence smem layout (bytes) ---------------------------------------
// W fp16 hi (64KB) | W fp16 lo (64KB) | A 2 x 32KB | zb [2][32][33] f32
#define SO_WHI   0
#define SO_WLO   65536
#define SO_A     131072          // 2 x 32768
#define SO_Z     196608          // [2][32][33] f32 = 8448
#define SMEM_R   205056

// ---------------------------------------------------------------------------
// fp32 -> bf16 hi/lo conversion (vectorized by 4)
// ---------------------------------------------------------------------------
__global__ void conv_hl(const float* __restrict__ src, __nv_bfloat16* __restrict__ hi,
                        __nv_bfloat16* __restrict__ lo, int n4)
{
    int i = blockIdx.x * blockDim.x + threadIdx.x;
    if (i < n4) {
        float4 v = ((const float4*)src)[i];
        __nv_bfloat16 h[4], l[4];
        float vv[4] = {v.x, v.y, v.z, v.w};
        #pragma unroll
        for (int j = 0; j < 4; j++) {
            h[j] = __float2bfloat16(vv[j]);
            l[j] = __float2bfloat16(vv[j] - __bfloat162float(h[j]));
        }
        ((uint64_t*)hi)[i] = *(uint64_t*)h;
        ((uint64_t*)lo)[i] = *(uint64_t*)l;
    }
}

// fp32 -> fp16 hi/lo conversion
__global__ void conv_hl16(const float* __restrict__ src, __half* __restrict__ hi,
                          __half* __restrict__ lo, int n4)
{
    int i = blockIdx.x * blockDim.x + threadIdx.x;
    if (i < n4) {
        float4 v = ((const float4*)src)[i];
        __half h[4], l[4];
        float vv[4] = {v.x, v.y, v.z, v.w};
        #pragma unroll
        for (int j = 0; j < 4; j++) {
            h[j] = __float2half_rn(vv[j]);
            l[j] = __float2half_rn(vv[j] - __half2float(h[j]));
        }
        ((uint64_t*)hi)[i] = *(uint64_t*)h;
        ((uint64_t*)lo)[i] = *(uint64_t*)l;
    }
}

// ---------------------------------------------------------------------------
// bf16 hi/lo GEMM (validated R10): C = (Ahi+Alo)@(Bhi+Blo) + bias, 3-term.
// Used only for XZ1 (obs-based, K=256).
// ---------------------------------------------------------------------------
template<int EPI>
__global__ __launch_bounds__(256, 2)
void gemm_bf16_hl(const __nv_bfloat16* __restrict__ Ahi, const __nv_bfloat16* __restrict__ Alo,
                  const __nv_bfloat16* __restrict__ Bhi, const __nv_bfloat16* __restrict__ Blo,
                  const float* __restrict__ bias, float* __restrict__ C,
                  int M, int N, int K, int ldc)
{
    __shared__ __align__(128) char sm[32768];
    const uint32_t sA = smem_u32(sm);
    const uint32_t sB = sA + 24576;

    const int tid  = threadIdx.x;
    const int wid  = tid >> 5;
    const int lane = tid & 31;
    const int mt   = wid >> 1;
    const int nh   = wid & 1;
    const int bm   = blockIdx.y * 128;
    const int bn   = blockIdx.x * 64;

    const int arow0 = mt * 32 + (lane & 7) + ((lane >> 3) & 1) * 8;
    const int a_u   = lane >> 4;
    const int kr    = lane & 15;
    const int nb0   = nh * 4 + (lane >> 4);
    const int nb1   = nh * 4 + 2 + (lane >> 4);

    float d[2][2][2][4];
    #pragma unroll
    for (int q = 0; q < 2; q++)
        #pragma unroll
        for (int s = 0; s < 2; s++)
            #pragma unroll
            for (int h8 = 0; h8 < 2; h8++)
                #pragma unroll
                for (int e = 0; e < 4; e++) d[q][s][h8][e] = 0.f;

    const int nk = K / 16;

    {
        #pragma unroll
        for (int i = 0; i < 2; i++) {
            int idx = tid + i * 256;
            int hl = idx >> 8, rem = idx & 255;
            int r = rem >> 1, u = rem & 1;
            const __nv_bfloat16* src = (hl ? Alo : Ahi) + (size_t)(bm + r) * K + u * 8;
            cp_async16(sm + hl * 6144 + r * 48 + u * 16, src);
        }
        {
            int hl = tid >> 7, rem = tid & 127;
            int kk = rem >> 3, nb = rem & 7;
            const __nv_bfloat16* src = (hl ? Blo : Bhi) + (size_t)kk * N + bn + nb * 8;
            cp_async16(sm + 24576 + hl * 2048 + kk * 128 + ((nb ^ (kk & 7)) * 16), src);
        }
        cp_commit();
    }

    for (int c = 0; c < nk; c++) {
        const int buf = c & 1;
        cp_wait<0>();
        __syncthreads();

        if (c + 1 < nk) {
            const int k0 = (c + 1) * 16;
            char* base = (char*)sm + ((buf ^ 1) ? 12288 : 0);
            #pragma unroll
            for (int i = 0; i < 2; i++) {
                int idx = tid + i * 256;
                int hl = idx >> 8, rem = idx & 255;
                int r = rem >> 1, u = rem & 1;
                const __nv_bfloat16* src = (hl ? Alo : Ahi) + (size_t)(bm + r) * K + k0 + u * 8;
                cp_async16(base + hl * 6144 + r * 48 + u * 16, src);
            }
            {
                int hl = tid >> 7, rem = tid & 127;
                int kk = rem >> 3, nb = rem & 7;
                const __nv_bfloat16* src = (hl ? Blo : Bhi) + (size_t)(k0 + kk) * N + bn + nb * 8;
                cp_async16((char*)sm + 24576 + ((buf ^ 1) ? 4096 : 0) + hl * 2048
                           + kk * 128 + ((nb ^ (kk & 7)) * 16), src);
            }
            cp_commit();
        }

        const uint32_t aB = sA + buf * 12288;
        const uint32_t bB = sB + buf * 4096;

        uint32_t ah[2][4], al[2][4], bh[2][4], bl[2][4];
        #pragma unroll
        for (int q = 0; q < 2; q++) {
            uint32_t ra = aB + (uint32_t)(arow0 + q * 16) * 48 + a_u * 16;
            ldsm_x4(ah[q][0], ah[q][1], ah[q][2], ah[q][3], ra);
            ldsm_x4(al[q][0], al[q][1], al[q][2], al[q][3], ra + 6144);
        }
        {
            uint32_t r0 = bB + (uint32_t)kr * 128 + ((nb0 ^ (kr & 7)) * 16);
            uint32_t r1 = bB + (uint32_t)kr * 128 + ((nb1 ^ (kr & 7)) * 16);
            ldsm_x4t(bh[0][0], bh[0][1], bh[0][2], bh[0][3], r0);
            ldsm_x4t(bh[1][0], bh[1][1], bh[1][2], bh[1][3], r1);
            ldsm_x4t(bl[0][0], bl[0][1], bl[0][2], bl[0][3], r0 + 2048);
            ldsm_x4t(bl[1][0], bl[1][1], bl[1][2], bl[1][3], r1 + 2048);
        }

        #pragma unroll
        for (int q = 0; q < 2; q++)
            #pragma unroll
            for (int s = 0; s < 2; s++) {
                mma16816(d[q][s][0], ah[q][0], ah[q][1], ah[q][2], ah[q][3], bh[s][0], bh[s][1]);
                mma16816(d[q][s][1], ah[q][0], ah[q][1], ah[q][2], ah[q][3], bh[s][2], bh[s][3]);
                mma16816(d[q][s][0], ah[q][0], ah[q][1], ah[q][2], ah[q][3], bl[s][0], bl[s][1]);
                mma16816(d[q][s][1], ah[q][0], ah[q][1], ah[q][2], ah[q][3], bl[s][2], bl[s][3]);
                mma16816(d[q][s][0], al[q][0], al[q][1], al[q][2], al[q][3], bh[s][0], bh[s][1]);
                mma16816(d[q][s][1], al[q][0], al[q][1], al[q][2], al[q][3], bh[s][2], bh[s][3]);
            }
        __syncthreads();
    }

    #pragma unroll
    for (int q = 0; q < 2; q++) {
        int row = bm + mt * 32 + q * 16 + (lane >> 2);
        #pragma unroll
        for (int s = 0; s < 2; s++) {
            #pragma unroll
            for (int h8 = 0; h8 < 2; h8++) {
                int col = bn + nh * 32 + s * 16 + h8 * 8 + (lane & 3) * 2;
                float b0 = bias[col], b1 = bias[col + 1];
                float v0 = d[q][s][h8][0] + b0;
                float v1 = d[q][s][h8][1] + b1;
                float v2 = d[q][s][h8][2] + b0;
                float v3 = d[q][s][h8][3] + b1;
                if (EPI == 1) {
                    v0 = (v0 > 20.f) ? v0 : log1pf(expf(v0));
                    v1 = (v1 > 20.f) ? v1 : log1pf(expf(v1));
                    v2 = (v2 > 20.f) ? v2 : log1pf(expf(v2));
                    v3 = (v3 > 20.f) ? v3 : log1pf(expf(v3));
                }
                *(float2*)&C[(size_t)row * ldc + col]       = make_float2(v0, v1);
                *(float2*)&C[(size_t)(row + 8) * ldc + col] = make_float2(v2, v3);
            }
        }
    }
}

// ---------------------------------------------------------------------------
// fp16 GEMM v2: C = A @ (Bhi+Blo) + bias.  128x128 block tile (doubles A
// reuse vs R15's 128x64). 8 warps = 4 mt x 2 nh; warp tile 32x64.
// A single fp16, B fp16 hi/lo (2-term), fp32 accum. BK=16, double-buffered.
// ---------------------------------------------------------------------------
template<int EPI>
__global__ __launch_bounds__(256, 2)
void gemm_f16(const __half* __restrict__ A,
              const __half* __restrict__ Bhi, const __half* __restrict__ Blo,
              const float* __restrict__ bias, float* __restrict__ C,
              int M, int N, int K, int ldc)
{
    // sA: 2 buf x 128 rows x 48B = 12288 ; sB: 2 buf x 2 hl x 16k x 256B = 16384
    __shared__ __align__(128) char sm[28672];
    const uint32_t sA = smem_u32(sm);
    const uint32_t sB = sA + 12288;

    const int tid  = threadIdx.x;
    const int wid  = tid >> 5;
    const int lane = tid & 31;
    const int mt   = wid >> 1;
    const int nh   = wid & 1;
    const int bm   = blockIdx.y * 128;
    const int bn   = blockIdx.x * 128;

    const int arow0 = mt * 32 + (lane & 7) + ((lane >> 3) & 1) * 8;
    const int a_u   = lane >> 4;
    const int kr    = lane & 15;

    float d[2][4][2][4];
    #pragma unroll
    for (int q = 0; q < 2; q++)
        #pragma unroll
        for (int s = 0; s < 4; s++)
            #pragma unroll
            for (int h8 = 0; h8 < 2; h8++)
                #pragma unroll
                for (int e = 0; e < 4; e++) d[q][s][h8][e] = 0.f;

    const int nk = K / 16;

    {   // prologue: k-tile 0 -> buf 0
        {
            int r = tid >> 1, u = tid & 1;
            cp_async16(sm + r * 48 + u * 16, A + (size_t)(bm + r) * K + u * 8);
        }
        #pragma unroll
        for (int i = 0; i < 2; i++) {
            int idx = tid + i * 256;
            int hl = idx >> 8, rem = idx & 255;
            int kk = rem >> 4, nb = rem & 15;
            const __half* src = (hl ? Blo : Bhi) + (size_t)kk * N + bn + nb * 8;
            cp_async16(sm + 12288 + hl * 4096 + kk * 256 + ((nb ^ (kk & 7)) * 16), src);
        }
        cp_commit();
    }

    for (int c = 0; c < nk; c++) {
        const int buf = c & 1;
        cp_wait<0>();
        __syncthreads();

        if (c + 1 < nk) {
            const int k0 = (c + 1) * 16;
            {
                int r = tid >> 1, u = tid & 1;
                cp_async16((char*)sm + ((buf ^ 1) ? 6144 : 0) + r * 48 + u * 16,
                           A + (size_t)(bm + r) * K + k0 + u * 8);
            }
            #pragma unroll
            for (int i = 0; i < 2; i++) {
                int idx = tid + i * 256;
                int hl = idx >> 8, rem = idx & 255;
                int kk = rem >> 4, nb = rem & 15;
                const __half* src = (hl ? Blo : Bhi) + (size_t)(k0 + kk) * N + bn + nb * 8;
                cp_async16((char*)sm + 12288 + ((buf ^ 1) ? 8192 : 0) + hl * 4096
                           + kk * 256 + ((nb ^ (kk & 7)) * 16), src);
            }
            cp_commit();
        }

        const uint32_t aB = sA + buf * 6144;
        const uint32_t bB = sB + buf * 8192;

        uint32_t ah[2][4];
        #pragma unroll
        for (int q = 0; q < 2; q++) {
            uint32_t ra = aB + (uint32_t)(arow0 + q * 16) * 48 + a_u * 16;
            ldsm_x4(ah[q][0], ah[q][1], ah[q][2], ah[q][3], ra);
        }

        #pragma unroll
        for (int s = 0; s < 4; s++) {
            const int nbs = nh * 8 + s * 2 + (lane >> 4);
            uint32_t rb = bB + (uint32_t)kr * 256 + ((nbs ^ (kr & 7)) * 16);
            uint32_t b0, b1, b2, b3;
            ldsm_x4t(b0, b1, b2, b3, rb);
            #pragma unroll
            for (int q = 0; q < 2; q++) {
                mma16816h(d[q][s][0], ah[q][0], ah[q][1], ah[q][2], ah[q][3], b0, b1);
                mma16816h(d[q][s][1], ah[q][0], ah[q][1], ah[q][2], ah[q][3], b2, b3);
            }
            ldsm_x4t(b0, b1, b2, b3, rb + 4096);
            #pragma unroll
            for (int q = 0; q < 2; q++) {
                mma16816h(d[q][s][0], ah[q][0], ah[q][1], ah[q][2], ah[q][3], b0, b1);
                mma16816h(d[q][s][1], ah[q][0], ah[q][1], ah[q][2], ah[q][3], b2, b3);
            }
        }
        __syncthreads();
    }

    #pragma unroll
    for (int q = 0; q < 2; q++) {
        int row = bm + mt * 32 + q * 16 + (lane >> 2);
        #pragma unroll
        for (int s = 0; s < 4; s++) {
            #pragma unroll
            for (int h8 = 0; h8 < 2; h8++) {
                int col = bn + nh * 64 + s * 16 + h8 * 8 + (lane & 3) * 2;
                float b0 = bias[col], b1 = bias[col + 1];
                float v0 = d[q][s][h8][0] + b0;
                float v1 = d[q][s][h8][1] + b1;
                float v2 = d[q][s][h8][2] + b0;
                float v3 = d[q][s][h8][3] + b1;
                if (EPI == 1) {
                    v0 = (v0 > 20.f) ? v0 : log1pf(expf(v0));
                    v1 = (v1 > 20.f) ? v1 : log1pf(expf(v1));
                    v2 = (v2 > 20.f) ? v2 : log1pf(expf(v2));
                    v3 = (v3 > 20.f) ? v3 : log1pf(expf(v3));
                }
                *(float2*)&C[(size_t)row * ldc + col]       = make_float2(v0, v1);
                *(float2*)&C[(size_t)(row + 8) * ldc + col] = make_float2(v2, v3);
            }
        }
    }
}

// ---------------------------------------------------------------------------
// Persistent warp-MMA LSTM layer v8: R15 core, but flag polling restricted to
// warps 0/1 (one per phase flag, concurrent) + one __syncthreads — removes
// the 1024-warp same-address L2 poll storm.
// ---------------------------------------------------------------------------
__global__ __launch_bounds__(NTH_R, 1)
void lstm_layer_mma(const float* __restrict__ Wh,   // [H, 4H]
                    const float* __restrict__ XZ)   // [B*T, 4H] (bias folded)
{
    extern __shared__ __align__(128) char smem[];
    const uint32_t sbase = smem_u32(smem);
    const uint32_t sWHI  = sbase + SO_WHI;
    const uint32_t sWLO  = sbase + SO_WLO;
    const uint32_t sA    = sbase + SO_A;
    float* zb = (float*)(smem + SO_Z);    // [2][32][33]

    const int tid  = threadIdx.x;
    const int wid  = tid >> 5;
    const int lane = tid & 31;
    const int u0   = blockIdx.x * 8;
    const int grp  = blockIdx.x >> 6;     // 2 producer groups of 64 blocks

    // epilogue identity
    const int eb = tid >> 3;      // batch row 0..31
    const int ej = tid & 7;       // unit index 0..7
    const size_t hrow = (size_t)eb * T_;

    // ---- one-time: W slice -> fp16 hi/lo, swizzled. col(n) = (n>>3)*H + u0 + (n&7)
    for (int idx = tid; idx < 32 * 1024; idx += NTH_R) {
        int n = idx & 31, k = idx >> 5;
        int gcol = (n >> 3) * H_ + u0 + (n & 7);
        float w = Wh[(size_t)k * FH_ + gcol];
        __half hi = __float2half_rn(w);
        __half lo = __float2half_rn(w - __half2float(hi));
        uint32_t off = SW_B(k, n >> 3) + (uint32_t)(n & 7) * 2;
        *(__half*)(smem + SO_WHI + off) = hi;
        *(__half*)(smem + SO_WLO + off) = lo;
    }

    float c_reg = 0.f;

    // =========================== t = 0 (h0 = 0) ============================
    {
        const float* xzp = XZ + hrow * FH_ + u0 + ej;
        float zi = __ldg(&xzp[0]);
        float zg = __ldg(&xzp[2 * H_]);
        float zo = __ldg(&xzp[3 * H_]);
        float iv = 1.f / (1.f + __expf(-zi));
        float eg = __expf(-2.f * zg); float gv = (1.f - eg) / (1.f + eg);
        float ov = 1.f / (1.f + __expf(-zo));
        c_reg = iv * gv;
        float ec = __expf(-2.f * c_reg); float tc = (1.f - ec) / (1.f + ec);
        float hv = ov * tc;
        g_H16[hrow * H_ + u0 + ej] = __float2half_rn(hv);
    }
    __syncthreads();
    if (tid == 0) red_rel_add(&g_flag[grp], 1u);   // arrival for step 0

    // warp tiling: warp = (kh 0-1, mt 0-1, nh 0-1)
    const int kh  = wid >> 2;
    const int wr  = wid & 3;
    const int mt  = wr >> 1;
    const int nh  = wr & 1;
    const int m_loc = mt * 16 + (lane & 7) + ((lane >> 3) & 1) * 8;  // 0..31
    const int krow  = (lane & 7) + ((lane >> 3) & 1) * 8;
    const int nb    = nh * 2 + (lane >> 4);
    const int uoff  = lane >> 4;
    float* zbk = zb + kh * (32 * 33);

    // =========================== main loop =================================
    for (int t = 1; t < T_; t++) {
        const unsigned target = 64u * (unsigned)t;

        // prefetch xz gate inputs (independent of flags)
        const float* xzp = XZ + (hrow + t) * FH_ + u0 + ej;
        float x_i = __ldg(&xzp[0]);
        float x_f = __ldg(&xzp[H_]);
        float x_g = __ldg(&xzp[2 * H_]);
        float x_o = __ldg(&xzp[3 * H_]);

        // flag waits: warp 0 polls flag[0], warp 1 polls flag[1] (concurrent)
        if (wid < 2) wait_flag(&g_flag[wid], target);
        __syncthreads();

        // stage phase 0 (units [0,512)) -> buf0
        #pragma unroll
        for (int i = 0; i < 8; i++) {
            int g = tid + i * 256;
            int r = g >> 6, cc = g & 63;
            cp_async16(smem + SO_A + SW_A2(r, cc),
                       (const char*)g_H16
                       + (((size_t)r * T_ + (t - 1)) * H_ + (size_t)cc * 8) * 2);
        }
        cp_commit();
        // stage phase 1 (units [512,1024)) -> buf1
        #pragma unroll
        for (int i = 0; i < 8; i++) {
            int g = tid + i * 256;
            int r = g >> 6, cc = g & 63;
            cp_async16(smem + SO_A + 32768 + SW_A2(r, cc),
                       (const char*)g_H16
                       + (((size_t)r * T_ + (t - 1)) * H_ + 512 + (size_t)cc * 8) * 2);
        }
        cp_commit();

        float d0[4] = {0.f, 0.f, 0.f, 0.f};
        float d1[4] = {0.f, 0.f, 0.f, 0.f};

        #pragma unroll 1
        for (int p = 0; p < 2; p++) {
            if (p == 0) cp_wait<1>(); else cp_wait<0>();
            __syncthreads();

            const uint32_t abase = sA + (uint32_t)p * 32768u;
            #pragma unroll
            for (int ks = 0; ks < 16; ks++) {
                const int ksg = kh * 16 + ks;             // k16 slice 0..31 in phase
                uint32_t a0, a1, a2, a3, b0, b1, b2, b3;
                ldsm_x4(a0, a1, a2, a3, abase + SW_A2(m_loc, ksg * 2 + uoff));
                int kk = p * 512 + ksg * 16 + krow;
                uint32_t boff = SW_B(kk, nb);
                ldsm_x4t(b0, b1, b2, b3, sWHI + boff);
                mma16816h(d0, a0, a1, a2, a3, b0, b1);
                mma16816h(d1, a0, a1, a2, a3, b2, b3);
                ldsm_x4t(b0, b1, b2, b3, sWLO + boff);
                mma16816h(d0, a0, a1, a2, a3, b0, b1);
                mma16816h(d1, a0, a1, a2, a3, b2, b3);
            }
        }

        // ---- d-frags -> zb[kh][32][33]
        {
            int row = mt * 16 + (lane >> 2);
            int col = nh * 16 + (lane & 3) * 2;
            zbk[row * 33 + col]           = d0[0];
            zbk[row * 33 + col + 1]       = d0[1];
            zbk[(row + 8) * 33 + col]     = d0[2];
            zbk[(row + 8) * 33 + col + 1] = d0[3];
            zbk[row * 33 + col + 8]       = d1[0];
            zbk[row * 33 + col + 9]       = d1[1];
            zbk[(row + 8) * 33 + col + 8] = d1[2];
            zbk[(row + 8) * 33 + col + 9] = d1[3];
        }
        __syncthreads();

        // ---- gates: all 256 threads, one (b, u) each; sum the two kh planes
        {
            const int base = eb * 33 + ej;
            float zi = zb[base]      + zb[32 * 33 + base]      + x_i;
            float zf = zb[base + 8]  + zb[32 * 33 + base + 8]  + x_f;
            float zg = zb[base + 16] + zb[32 * 33 + base + 16] + x_g;
            float zo = zb[base + 24] + zb[32 * 33 + base + 24] + x_o;

            float iv = 1.f / (1.f + __expf(-zi));
            float fv = 1.f / (1.f + __expf(-zf));
            float eg = __expf(-2.f * zg); float gv = (1.f - eg) / (1.f + eg);
            float ov = 1.f / (1.f + __expf(-zo));
            c_reg = fv * c_reg + iv * gv;
            float ec = __expf(-2.f * c_reg); float tc = (1.f - ec) / (1.f + ec);
            float hv = ov * tc;

            g_H16[(hrow + t) * H_ + u0 + ej] = __float2half_rn(hv);
        }

        __syncthreads();
        if (tid == 0) red_rel_add(&g_flag[grp], 1u);   // arrival for step t
    }
}

// ---------------------------------------------------------------------------
extern "C" void kernel_launch(void* const* d_in, const int* in_sizes, int n_in,
                              void* d_out, int out_size)
{
    const float* obs = (const float*)d_in[0];
    const float* W1x = (const float*)d_in[1];
    const float* W1h = (const float*)d_in[2];
    const float* b1  = (const float*)d_in[3];
    const float* W2x = (const float*)d_in[4];
    const float* W2h = (const float*)d_in[5];
    const float* b2  = (const float*)d_in[6];
    const float* Wm  = (const float*)d_in[7];
    const float* bm  = (const float*)d_in[8];
    const float* Wc  = (const float*)d_in[9];
    const float* bc  = (const float*)d_in[10];

    float* XZ;
    __half *H16, *w2xh, *w2xl, *wmh, *wml, *wch, *wcl;
    __nv_bfloat16 *obsh, *obsl, *w1xh, *w1xl;
    cudaGetSymbolAddress((void**)&XZ,   g_XZ);
    cudaGetSymbolAddress((void**)&H16,  g_H16);
    cudaGetSymbolAddress((void**)&obsh, g_obs_h);
    cudaGetSymbolAddress((void**)&obsl, g_obs_l);
    cudaGetSymbolAddress((void**)&w1xh, g_W1x_h);
    cudaGetSymbolAddress((void**)&w1xl, g_W1x_l);
    cudaGetSymbolAddress((void**)&w2xh, g_W2x_h);
    cudaGetSymbolAddress((void**)&w2xl, g_W2x_l);
    cudaGetSymbolAddress((void**)&wmh,  g_Wm_h);
    cudaGetSymbolAddress((void**)&wml,  g_Wm_l);
    cudaGetSymbolAddress((void**)&wch,  g_Wc_h);
    cudaGetSymbolAddress((void**)&wcl,  g_Wc_l);

    float* out = (float*)d_out;
    size_t half = (size_t)out_size / 2;   // mean | cov

    cudaFuncSetAttribute(lstm_layer_mma,
                         cudaFuncAttributeMaxDynamicSharedMemorySize, SMEM_R);

    // ---- conversions
    conv_hl  <<<(BT_*DIN_/4 + 255)/256, 256>>>(obs, obsh, obsl, BT_*DIN_/4);
    conv_hl  <<<(DIN_*FH_/4 + 255)/256, 256>>>(W1x, w1xh, w1xl, DIN_*FH_/4);
    conv_hl16<<<(H_*FH_/4   + 255)/256, 256>>>(W2x, w2xh, w2xl, H_*FH_/4);
    conv_hl16<<<(H_*DOUT_/4 + 255)/256, 256>>>(Wm,  wmh,  wml,  H_*DOUT_/4);
    conv_hl16<<<(H_*DOUT_/4 + 255)/256, 256>>>(Wc,  wch,  wcl,  H_*DOUT_/4);

    // XZ1 = obs @ W1x + b1   (bf16 3-term, full input precision)
    gemm_bf16_hl<0><<<dim3(FH_/64, BT_/128), 256>>>(obsh, obsl, w1xh, w1xl, b1, XZ,
                                                    BT_, FH_, DIN_, FH_);

    // Layer 1 recurrence -> g_H16 = H1 (fp16)
    zero_flags<<<1, 32>>>();
    lstm_layer_mma<<<NBLK_, NTH_R, SMEM_R>>>(W1h, XZ);

    // XZ2 = H1 @ W2x + b2   (fp16 A, fp16 hi/lo W, 128x128 tile)
    gemm_f16<0><<<dim3(FH_/128, BT_/128), 256>>>(H16, w2xh, w2xl, b2, XZ,
                                                 BT_, FH_, H_, FH_);

    // Layer 2 recurrence -> g_H16 = H2
    zero_flags<<<1, 32>>>();
    lstm_layer_mma<<<NBLK_, NTH_R, SMEM_R>>>(W2h, XZ);

    // Heads: mean = H2@Wm + bm ; cov = softplus(H2@Wc + bc)
    gemm_f16<0><<<dim3(DOUT_/128, BT_/128), 256>>>(H16, wmh, wml, bm, out,
                                                   BT_, DOUT_, H_, DOUT_);
    gemm_f16<1><<<dim3(DOUT_/128, BT_/128), 256>>>(H16, wch, wcl, bc, out + half,
                                                   BT_, DOUT_, H_, DOUT_);
}

// round 17
// speedup vs baseline: 2.0410x; 1.1461x over previous
#include <cuda_runtime.h>
#include <cuda_bf16.h>
#include <cuda_fp16.h>
#include <math.h>
#include <stdint.h>

#define B_    32
#define T_    1024
#define H_    1024
#define FH_   4096
#define DIN_  256
#define DOUT_ 512
#define BT_   (B_*T_)
#define NBLK_ 128
#define NTH_R 256

// -------- scratch (static device globals; no allocation anywhere) ----------
__device__ float g_XZ[(size_t)BT_*FH_];        // 512 MB, xz for current layer
__device__ __half g_H16[(size_t)BT_*H_];       // unified layer output, fp16 [B,T,H]
// converted operands
__device__ __nv_bfloat16 g_obs_h[(size_t)BT_*DIN_], g_obs_l[(size_t)BT_*DIN_];
__device__ __nv_bfloat16 g_W1x_h[(size_t)DIN_*FH_], g_W1x_l[(size_t)DIN_*FH_];
__device__ __half g_W2x_h[(size_t)H_*FH_];                         // single fp16
__device__ __half g_Wm_h[(size_t)H_*DOUT_],  g_Wm_l[(size_t)H_*DOUT_];
__device__ __half g_Wc_h[(size_t)H_*DOUT_],  g_Wc_l[(size_t)H_*DOUT_];

// producer/consumer phase flags: flag[g] = monotonic arrival count of block
// group g (blocks 64g..64g+63, producing h units [512g, 512g+512)).
__device__ unsigned g_flag[4];

__global__ void zero_flags()
{
    if (threadIdx.x < 4) g_flag[threadIdx.x] = 0;
}

__device__ __forceinline__ unsigned ld_acq(const unsigned* p)
{
    unsigned v;
    asm volatile("ld.acquire.gpu.u32 %0, [%1];" : "=r"(v) : "l"(p) : "memory");
    return v;
}
__device__ __forceinline__ void red_rel_add(unsigned* p, unsigned v)
{
    asm volatile("red.release.gpu.add.u32 [%0], %1;" :: "l"(p), "r"(v) : "memory");
}
__device__ __forceinline__ void wait_flag(const unsigned* p, unsigned target)
{
    while (ld_acq(p) < target) { }
}

// ---- cp.async helpers -----------------------------------------------------
__device__ __forceinline__ void cp_async16(void* sptr, const void* gptr)
{
    unsigned sa = (unsigned)__cvta_generic_to_shared(sptr);
    asm volatile("cp.async.cg.shared.global [%0], [%1], 16;" :: "r"(sa), "l"(gptr));
}
__device__ __forceinline__ void cp_commit()
{
    asm volatile("cp.async.commit_group;" ::: "memory");
}
template<int N> __device__ __forceinline__ void cp_wait()
{
    asm volatile("cp.async.wait_group %0;" :: "n"(N) : "memory");
}

// ---- warp-MMA helpers -----------------------------------------------------
__device__ __forceinline__ uint32_t smem_u32(const void* p)
{
    uint32_t a;
    asm("{ .reg .u64 t; cvta.to.shared.u64 t, %1; cvt.u32.u64 %0, t; }" : "=r"(a) : "l"(p));
    return a;
}
__device__ __forceinline__ void ldsm_x4(uint32_t& r0, uint32_t& r1, uint32_t& r2, uint32_t& r3,
                                        uint32_t addr)
{
    asm volatile("ldmatrix.sync.aligned.m8n8.x4.shared.b16 {%0,%1,%2,%3}, [%4];"
                 : "=r"(r0), "=r"(r1), "=r"(r2), "=r"(r3) : "r"(addr));
}
__device__ __forceinline__ void ldsm_x4t(uint32_t& r0, uint32_t& r1, uint32_t& r2, uint32_t& r3,
                                         uint32_t addr)
{
    asm volatile("ldmatrix.sync.aligned.m8n8.x4.trans.shared.b16 {%0,%1,%2,%3}, [%4];"
                 : "=r"(r0), "=r"(r1), "=r"(r2), "=r"(r3) : "r"(addr));
}
__device__ __forceinline__ void mma16816(float* d,
                                         uint32_t a0, uint32_t a1, uint32_t a2, uint32_t a3,
                                         uint32_t b0, uint32_t b1)
{
    asm volatile("mma.sync.aligned.m16n8k16.row.col.f32.bf16.bf16.f32 "
                 "{%0,%1,%2,%3}, {%4,%5,%6,%7}, {%8,%9}, {%0,%1,%2,%3};"
                 : "+f"(d[0]), "+f"(d[1]), "+f"(d[2]), "+f"(d[3])
                 : "r"(a0), "r"(a1), "r"(a2), "r"(a3), "r"(b0), "r"(b1));
}
__device__ __forceinline__ void mma16816h(float* d,
                                          uint32_t a0, uint32_t a1, uint32_t a2, uint32_t a3,
                                          uint32_t b0, uint32_t b1)
{
    asm volatile("mma.sync.aligned.m16n8k16.row.col.f32.f16.f16.f32 "
                 "{%0,%1,%2,%3}, {%4,%5,%6,%7}, {%8,%9}, {%0,%1,%2,%3};"
                 : "+f"(d[0]), "+f"(d[1]), "+f"(d[2]), "+f"(d[3])
                 : "r"(a0), "r"(a1), "r"(a2), "r"(a3), "r"(b0), "r"(b1));
}

// swizzles
#define SW_B(k, nb) ((uint32_t)(k) * 64u + (uint32_t)((((nb) ^ (((k) >> 1) & 3))) * 16))
// A phase tile [32 m][64 units of 16B] (1KB rows)
#define SW_A2(m, unit) ((uint32_t)(m) * 1024u + (uint32_t)((((unit) ^ ((m) & 7))) * 16))

// ---- recurrence smem layout (bytes) ---------------------------------------
// W fp16 (64KB) | A 2 x 32KB | zb [2][32][33] f32
#define SO_WHI   0
#define SO_A     65536           // 2 x 32768
#define SO_Z     131072          // [2][32][33] f32 = 8448
#define SMEM_R   139520

// ---------------------------------------------------------------------------
// fp32 -> bf16 hi/lo conversion (vectorized by 4)
// ---------------------------------------------------------------------------
__global__ void conv_hl(const float* __restrict__ src, __nv_bfloat16* __restrict__ hi,
                        __nv_bfloat16* __restrict__ lo, int n4)
{
    int i = blockIdx.x * blockDim.x + threadIdx.x;
    if (i < n4) {
        float4 v = ((const float4*)src)[i];
        __nv_bfloat16 h[4], l[4];
        float vv[4] = {v.x, v.y, v.z, v.w};
        #pragma unroll
        for (int j = 0; j < 4; j++) {
            h[j] = __float2bfloat16(vv[j]);
            l[j] = __float2bfloat16(vv[j] - __bfloat162float(h[j]));
        }
        ((uint64_t*)hi)[i] = *(uint64_t*)h;
        ((uint64_t*)lo)[i] = *(uint64_t*)l;
    }
}

// fp32 -> fp16 hi/lo conversion
__global__ void conv_hl16(const float* __restrict__ src, __half* __restrict__ hi,
                          __half* __restrict__ lo, int n4)
{
    int i = blockIdx.x * blockDim.x + threadIdx.x;
    if (i < n4) {
        float4 v = ((const float4*)src)[i];
        __half h[4], l[4];
        float vv[4] = {v.x, v.y, v.z, v.w};
        #pragma unroll
        for (int j = 0; j < 4; j++) {
            h[j] = __float2half_rn(vv[j]);
            l[j] = __float2half_rn(vv[j] - __half2float(h[j]));
        }
        ((uint64_t*)hi)[i] = *(uint64_t*)h;
        ((uint64_t*)lo)[i] = *(uint64_t*)l;
    }
}

// fp32 -> fp16 single conversion
__global__ void conv_f16(const float* __restrict__ src, __half* __restrict__ dst, int n4)
{
    int i = blockIdx.x * blockDim.x + threadIdx.x;
    if (i < n4) {
        float4 v = ((const float4*)src)[i];
        __half h[4] = {__float2half_rn(v.x), __float2half_rn(v.y),
                       __float2half_rn(v.z), __float2half_rn(v.w)};
        ((uint64_t*)dst)[i] = *(uint64_t*)h;
    }
}

// ---------------------------------------------------------------------------
// bf16 hi/lo GEMM (validated R10): C = (Ahi+Alo)@(Bhi+Blo) + bias, 3-term.
// Used only for XZ1 (obs-based, K=256).
// ---------------------------------------------------------------------------
template<int EPI>
__global__ __launch_bounds__(256, 2)
void gemm_bf16_hl(const __nv_bfloat16* __restrict__ Ahi, const __nv_bfloat16* __restrict__ Alo,
                  const __nv_bfloat16* __restrict__ Bhi, const __nv_bfloat16* __restrict__ Blo,
                  const float* __restrict__ bias, float* __restrict__ C,
                  int M, int N, int K, int ldc)
{
    __shared__ __align__(128) char sm[32768];
    const uint32_t sA = smem_u32(sm);
    const uint32_t sB = sA + 24576;

    const int tid  = threadIdx.x;
    const int wid  = tid >> 5;
    const int lane = tid & 31;
    const int mt   = wid >> 1;
    const int nh   = wid & 1;
    const int bm   = blockIdx.y * 128;
    const int bn   = blockIdx.x * 64;

    const int arow0 = mt * 32 + (lane & 7) + ((lane >> 3) & 1) * 8;
    const int a_u   = lane >> 4;
    const int kr    = lane & 15;
    const int nb0   = nh * 4 + (lane >> 4);
    const int nb1   = nh * 4 + 2 + (lane >> 4);

    float d[2][2][2][4];
    #pragma unroll
    for (int q = 0; q < 2; q++)
        #pragma unroll
        for (int s = 0; s < 2; s++)
            #pragma unroll
            for (int h8 = 0; h8 < 2; h8++)
                #pragma unroll
                for (int e = 0; e < 4; e++) d[q][s][h8][e] = 0.f;

    const int nk = K / 16;

    {
        #pragma unroll
        for (int i = 0; i < 2; i++) {
            int idx = tid + i * 256;
            int hl = idx >> 8, rem = idx & 255;
            int r = rem >> 1, u = rem & 1;
            const __nv_bfloat16* src = (hl ? Alo : Ahi) + (size_t)(bm + r) * K + u * 8;
            cp_async16(sm + hl * 6144 + r * 48 + u * 16, src);
        }
        {
            int hl = tid >> 7, rem = tid & 127;
            int kk = rem >> 3, nb = rem & 7;
            const __nv_bfloat16* src = (hl ? Blo : Bhi) + (size_t)kk * N + bn + nb * 8;
            cp_async16(sm + 24576 + hl * 2048 + kk * 128 + ((nb ^ (kk & 7)) * 16), src);
        }
        cp_commit();
    }

    for (int c = 0; c < nk; c++) {
        const int buf = c & 1;
        cp_wait<0>();
        __syncthreads();

        if (c + 1 < nk) {
            const int k0 = (c + 1) * 16;
            char* base = (char*)sm + ((buf ^ 1) ? 12288 : 0);
            #pragma unroll
            for (int i = 0; i < 2; i++) {
                int idx = tid + i * 256;
                int hl = idx >> 8, rem = idx & 255;
                int r = rem >> 1, u = rem & 1;
                const __nv_bfloat16* src = (hl ? Alo : Ahi) + (size_t)(bm + r) * K + k0 + u * 8;
                cp_async16(base + hl * 6144 + r * 48 + u * 16, src);
            }
            {
                int hl = tid >> 7, rem = tid & 127;
                int kk = rem >> 3, nb = rem & 7;
                const __nv_bfloat16* src = (hl ? Blo : Bhi) + (size_t)(k0 + kk) * N + bn + nb * 8;
                cp_async16((char*)sm + 24576 + ((buf ^ 1) ? 4096 : 0) + hl * 2048
                           + kk * 128 + ((nb ^ (kk & 7)) * 16), src);
            }
            cp_commit();
        }

        const uint32_t aB = sA + buf * 12288;
        const uint32_t bB = sB + buf * 4096;

        uint32_t ah[2][4], al[2][4], bh[2][4], bl[2][4];
        #pragma unroll
        for (int q = 0; q < 2; q++) {
            uint32_t ra = aB + (uint32_t)(arow0 + q * 16) * 48 + a_u * 16;
            ldsm_x4(ah[q][0], ah[q][1], ah[q][2], ah[q][3], ra);
            ldsm_x4(al[q][0], al[q][1], al[q][2], al[q][3], ra + 6144);
        }
        {
            uint32_t r0 = bB + (uint32_t)kr * 128 + ((nb0 ^ (kr & 7)) * 16);
            uint32_t r1 = bB + (uint32_t)kr * 128 + ((nb1 ^ (kr & 7)) * 16);
            ldsm_x4t(bh[0][0], bh[0][1], bh[0][2], bh[0][3], r0);
            ldsm_x4t(bh[1][0], bh[1][1], bh[1][2], bh[1][3], r1);
            ldsm_x4t(bl[0][0], bl[0][1], bl[0][2], bl[0][3], r0 + 2048);
            ldsm_x4t(bl[1][0], bl[1][1], bl[1][2], bl[1][3], r1 + 2048);
        }

        #pragma unroll
        for (int q = 0; q < 2; q++)
            #pragma unroll
            for (int s = 0; s < 2; s++) {
                mma16816(d[q][s][0], ah[q][0], ah[q][1], ah[q][2], ah[q][3], bh[s][0], bh[s][1]);
                mma16816(d[q][s][1], ah[q][0], ah[q][1], ah[q][2], ah[q][3], bh[s][2], bh[s][3]);
                mma16816(d[q][s][0], ah[q][0], ah[q][1], ah[q][2], ah[q][3], bl[s][0], bl[s][1]);
                mma16816(d[q][s][1], ah[q][0], ah[q][1], ah[q][2], ah[q][3], bl[s][2], bl[s][3]);
                mma16816(d[q][s][0], al[q][0], al[q][1], al[q][2], al[q][3], bh[s][0], bh[s][1]);
                mma16816(d[q][s][1], al[q][0], al[q][1], al[q][2], al[q][3], bh[s][2], bh[s][3]);
            }
        __syncthreads();
    }

    #pragma unroll
    for (int q = 0; q < 2; q++) {
        int row = bm + mt * 32 + q * 16 + (lane >> 2);
        #pragma unroll
        for (int s = 0; s < 2; s++) {
            #pragma unroll
            for (int h8 = 0; h8 < 2; h8++) {
                int col = bn + nh * 32 + s * 16 + h8 * 8 + (lane & 3) * 2;
                float b0 = bias[col], b1 = bias[col + 1];
                float v0 = d[q][s][h8][0] + b0;
                float v1 = d[q][s][h8][1] + b1;
                float v2 = d[q][s][h8][2] + b0;
                float v3 = d[q][s][h8][3] + b1;
                if (EPI == 1) {
                    v0 = (v0 > 20.f) ? v0 : log1pf(expf(v0));
                    v1 = (v1 > 20.f) ? v1 : log1pf(expf(v1));
                    v2 = (v2 > 20.f) ? v2 : log1pf(expf(v2));
                    v3 = (v3 > 20.f) ? v3 : log1pf(expf(v3));
                }
                *(float2*)&C[(size_t)row * ldc + col]       = make_float2(v0, v1);
                *(float2*)&C[(size_t)(row + 8) * ldc + col] = make_float2(v2, v3);
            }
        }
    }
}

// ---------------------------------------------------------------------------
// fp16 GEMM: C = A @ B + bias.  NBT=2: B = Bhi+Blo (2-term). NBT=1: B single.
// 128x128 block tile, 8 warps = 4 mt x 2 nh; warp tile 32x64. fp32 accum.
// ---------------------------------------------------------------------------
template<int EPI, int NBT>
__global__ __launch_bounds__(256, 2)
void gemm_f16(const __half* __restrict__ A,
              const __half* __restrict__ Bhi, const __half* __restrict__ Blo,
              const float* __restrict__ bias, float* __restrict__ C,
              int M, int N, int K, int ldc)
{
    // sA: 2 buf x 128 rows x 48B = 12288 ; sB: 2 buf x (up to 2 hl) x 4096
    __shared__ __align__(128) char sm[28672];
    const uint32_t sA = smem_u32(sm);
    const uint32_t sB = sA + 12288;

    const int tid  = threadIdx.x;
    const int wid  = tid >> 5;
    const int lane = tid & 31;
    const int mt   = wid >> 1;
    const int nh   = wid & 1;
    const int bm   = blockIdx.y * 128;
    const int bn   = blockIdx.x * 128;

    const int arow0 = mt * 32 + (lane & 7) + ((lane >> 3) & 1) * 8;
    const int a_u   = lane >> 4;
    const int kr    = lane & 15;

    float d[2][4][2][4];
    #pragma unroll
    for (int q = 0; q < 2; q++)
        #pragma unroll
        for (int s = 0; s < 4; s++)
            #pragma unroll
            for (int h8 = 0; h8 < 2; h8++)
                #pragma unroll
                for (int e = 0; e < 4; e++) d[q][s][h8][e] = 0.f;

    const int nk = K / 16;

    {   // prologue: k-tile 0 -> buf 0
        {
            int r = tid >> 1, u = tid & 1;
            cp_async16(sm + r * 48 + u * 16, A + (size_t)(bm + r) * K + u * 8);
        }
        if (NBT == 2) {
            #pragma unroll
            for (int i = 0; i < 2; i++) {
                int idx = tid + i * 256;
                int hl = idx >> 8, rem = idx & 255;
                int kk = rem >> 4, nb = rem & 15;
                const __half* src = (hl ? Blo : Bhi) + (size_t)kk * N + bn + nb * 8;
                cp_async16(sm + 12288 + hl * 4096 + kk * 256 + ((nb ^ (kk & 7)) * 16), src);
            }
        } else {
            int kk = tid >> 4, nb = tid & 15;
            const __half* src = Bhi + (size_t)kk * N + bn + nb * 8;
            cp_async16(sm + 12288 + kk * 256 + ((nb ^ (kk & 7)) * 16), src);
        }
        cp_commit();
    }

    for (int c = 0; c < nk; c++) {
        const int buf = c & 1;
        cp_wait<0>();
        __syncthreads();

        if (c + 1 < nk) {
            const int k0 = (c + 1) * 16;
            {
                int r = tid >> 1, u = tid & 1;
                cp_async16((char*)sm + ((buf ^ 1) ? 6144 : 0) + r * 48 + u * 16,
                           A + (size_t)(bm + r) * K + k0 + u * 8);
            }
            if (NBT == 2) {
                #pragma unroll
                for (int i = 0; i < 2; i++) {
                    int idx = tid + i * 256;
                    int hl = idx >> 8, rem = idx & 255;
                    int kk = rem >> 4, nb = rem & 15;
                    const __half* src = (hl ? Blo : Bhi) + (size_t)(k0 + kk) * N + bn + nb * 8;
                    cp_async16((char*)sm + 12288 + ((buf ^ 1) ? 8192 : 0) + hl * 4096
                               + kk * 256 + ((nb ^ (kk & 7)) * 16), src);
                }
            } else {
                int kk = tid >> 4, nb = tid & 15;
                const __half* src = Bhi + (size_t)(k0 + kk) * N + bn + nb * 8;
                cp_async16((char*)sm + 12288 + ((buf ^ 1) ? 8192 : 0)
                           + kk * 256 + ((nb ^ (kk & 7)) * 16), src);
            }
            cp_commit();
        }

        const uint32_t aB = sA + buf * 6144;
        const uint32_t bB = sB + buf * 8192;

        uint32_t ah[2][4];
        #pragma unroll
        for (int q = 0; q < 2; q++) {
            uint32_t ra = aB + (uint32_t)(arow0 + q * 16) * 48 + a_u * 16;
            ldsm_x4(ah[q][0], ah[q][1], ah[q][2], ah[q][3], ra);
        }

        #pragma unroll
        for (int s = 0; s < 4; s++) {
            const int nbs = nh * 8 + s * 2 + (lane >> 4);
            uint32_t rb = bB + (uint32_t)kr * 256 + ((nbs ^ (kr & 7)) * 16);
            uint32_t b0, b1, b2, b3;
            ldsm_x4t(b0, b1, b2, b3, rb);
            #pragma unroll
            for (int q = 0; q < 2; q++) {
                mma16816h(d[q][s][0], ah[q][0], ah[q][1], ah[q][2], ah[q][3], b0, b1);
                mma16816h(d[q][s][1], ah[q][0], ah[q][1], ah[q][2], ah[q][3], b2, b3);
            }
            if (NBT == 2) {
                ldsm_x4t(b0, b1, b2, b3, rb + 4096);
                #pragma unroll
                for (int q = 0; q < 2; q++) {
                    mma16816h(d[q][s][0], ah[q][0], ah[q][1], ah[q][2], ah[q][3], b0, b1);
                    mma16816h(d[q][s][1], ah[q][0], ah[q][1], ah[q][2], ah[q][3], b2, b3);
                }
            }
        }
        __syncthreads();
    }

    #pragma unroll
    for (int q = 0; q < 2; q++) {
        int row = bm + mt * 32 + q * 16 + (lane >> 2);
        #pragma unroll
        for (int s = 0; s < 4; s++) {
            #pragma unroll
            for (int h8 = 0; h8 < 2; h8++) {
                int col = bn + nh * 64 + s * 16 + h8 * 8 + (lane & 3) * 2;
                float b0 = bias[col], b1 = bias[col + 1];
                float v0 = d[q][s][h8][0] + b0;
                float v1 = d[q][s][h8][1] + b1;
                float v2 = d[q][s][h8][2] + b0;
                float v3 = d[q][s][h8][3] + b1;
                if (EPI == 1) {
                    v0 = (v0 > 20.f) ? v0 : log1pf(expf(v0));
                    v1 = (v1 > 20.f) ? v1 : log1pf(expf(v1));
                    v2 = (v2 > 20.f) ? v2 : log1pf(expf(v2));
                    v3 = (v3 > 20.f) ? v3 : log1pf(expf(v3));
                }
                *(float2*)&C[(size_t)row * ldc + col]       = make_float2(v0, v1);
                *(float2*)&C[(size_t)(row + 8) * ldc + col] = make_float2(v2, v3);
            }
        }
    }
}

// ---------------------------------------------------------------------------
// Persistent warp-MMA LSTM layer v9: h fp16 (M=32), W single fp16 (64KB smem,
// halved mma vs v8). 256 threads, 8 warps = (kh 0-1)(mt 0-1)(nh 0-1).
// 2-phase (512 k) double-buffered A staging; phase-flag sync.
// ---------------------------------------------------------------------------
__global__ __launch_bounds__(NTH_R, 1)
void lstm_layer_mma(const float* __restrict__ Wh,   // [H, 4H]
                    const float* __restrict__ XZ)   // [B*T, 4H] (bias folded)
{
    extern __shared__ __align__(128) char smem[];
    const uint32_t sbase = smem_u32(smem);
    const uint32_t sWHI  = sbase + SO_WHI;
    const uint32_t sA    = sbase + SO_A;
    float* zb = (float*)(smem + SO_Z);    // [2][32][33]

    const int tid  = threadIdx.x;
    const int wid  = tid >> 5;
    const int lane = tid & 31;
    const int u0   = blockIdx.x * 8;
    const int grp  = blockIdx.x >> 6;     // 2 producer groups of 64 blocks

    // epilogue identity
    const int eb = tid >> 3;      // batch row 0..31
    const int ej = tid & 7;       // unit index 0..7
    const size_t hrow = (size_t)eb * T_;

    // ---- one-time: W slice -> single fp16, swizzled. col(n) = (n>>3)*H + u0 + (n&7)
    for (int idx = tid; idx < 32 * 1024; idx += NTH_R) {
        int n = idx & 31, k = idx >> 5;
        int gcol = (n >> 3) * H_ + u0 + (n & 7);
        float w = Wh[(size_t)k * FH_ + gcol];
        uint32_t off = SW_B(k, n >> 3) + (uint32_t)(n & 7) * 2;
        *(__half*)(smem + SO_WHI + off) = __float2half_rn(w);
    }

    float c_reg = 0.f;

    // =========================== t = 0 (h0 = 0) ============================
    {
        const float* xzp = XZ + hrow * FH_ + u0 + ej;
        float zi = __ldg(&xzp[0]);
        float zg = __ldg(&xzp[2 * H_]);
        float zo = __ldg(&xzp[3 * H_]);
        float iv = 1.f / (1.f + __expf(-zi));
        float eg = __expf(-2.f * zg); float gv = (1.f - eg) / (1.f + eg);
        float ov = 1.f / (1.f + __expf(-zo));
        c_reg = iv * gv;
        float ec = __expf(-2.f * c_reg); float tc = (1.f - ec) / (1.f + ec);
        float hv = ov * tc;
        g_H16[hrow * H_ + u0 + ej] = __float2half_rn(hv);
    }
    __syncthreads();
    if (tid == 0) red_rel_add(&g_flag[grp], 1u);   // arrival for step 0

    // warp tiling: warp = (kh 0-1, mt 0-1, nh 0-1)
    const int kh  = wid >> 2;
    const int wr  = wid & 3;
    const int mt  = wr >> 1;
    const int nh  = wr & 1;
    const int m_loc = mt * 16 + (lane & 7) + ((lane >> 3) & 1) * 8;  // 0..31
    const int krow  = (lane & 7) + ((lane >> 3) & 1) * 8;
    const int nb    = nh * 2 + (lane >> 4);
    const int uoff  = lane >> 4;
    float* zbk = zb + kh * (32 * 33);

    // =========================== main loop =================================
    for (int t = 1; t < T_; t++) {
        const unsigned target = 64u * (unsigned)t;

        // prefetch xz gate inputs (independent of flags)
        const float* xzp = XZ + (hrow + t) * FH_ + u0 + ej;
        float x_i = __ldg(&xzp[0]);
        float x_f = __ldg(&xzp[H_]);
        float x_g = __ldg(&xzp[2 * H_]);
        float x_o = __ldg(&xzp[3 * H_]);

        // flag waits: warp 0 polls flag[0], warp 1 polls flag[1] (concurrent)
        if (wid < 2) wait_flag(&g_flag[wid], target);
        __syncthreads();

        // stage phase 0 (units [0,512)) -> buf0
        #pragma unroll
        for (int i = 0; i < 8; i++) {
            int g = tid + i * 256;
            int r = g >> 6, cc = g & 63;
            cp_async16(smem + SO_A + SW_A2(r, cc),
                       (const char*)g_H16
                       + (((size_t)r * T_ + (t - 1)) * H_ + (size_t)cc * 8) * 2);
        }
        cp_commit();
        // stage phase 1 (units [512,1024)) -> buf1
        #pragma unroll
        for (int i = 0; i < 8; i++) {
            int g = tid + i * 256;
            int r = g >> 6, cc = g & 63;
            cp_async16(smem + SO_A + 32768 + SW_A2(r, cc),
                       (const char*)g_H16
                       + (((size_t)r * T_ + (t - 1)) * H_ + 512 + (size_t)cc * 8) * 2);
        }
        cp_commit();

        float d0[4] = {0.f, 0.f, 0.f, 0.f};
        float d1[4] = {0.f, 0.f, 0.f, 0.f};

        #pragma unroll 1
        for (int p = 0; p < 2; p++) {
            if (p == 0) cp_wait<1>(); else cp_wait<0>();
            __syncthreads();

            const uint32_t abase = sA + (uint32_t)p * 32768u;
            #pragma unroll
            for (int ks = 0; ks < 16; ks++) {
                const int ksg = kh * 16 + ks;             // k16 slice 0..31 in phase
                uint32_t a0, a1, a2, a3, b0, b1, b2, b3;
                ldsm_x4(a0, a1, a2, a3, abase + SW_A2(m_loc, ksg * 2 + uoff));
                int kk = p * 512 + ksg * 16 + krow;
                ldsm_x4t(b0, b1, b2, b3, sWHI + SW_B(kk, nb));
                mma16816h(d0, a0, a1, a2, a3, b0, b1);
                mma16816h(d1, a0, a1, a2, a3, b2, b3);
            }
        }

        // ---- d-frags -> zb[kh][32][33]
        {
            int row = mt * 16 + (lane >> 2);
            int col = nh * 16 + (lane & 3) * 2;
            zbk[row * 33 + col]           = d0[0];
            zbk[row * 33 + col + 1]       = d0[1];
            zbk[(row + 8) * 33 + col]     = d0[2];
            zbk[(row + 8) * 33 + col + 1] = d0[3];
            zbk[row * 33 + col + 8]       = d1[0];
            zbk[row * 33 + col + 9]       = d1[1];
            zbk[(row + 8) * 33 + col + 8] = d1[2];
            zbk[(row + 8) * 33 + col + 9] = d1[3];
        }
        __syncthreads();

        // ---- gates: all 256 threads, one (b, u) each; sum the two kh planes
        {
            const int base = eb * 33 + ej;
            float zi = zb[base]      + zb[32 * 33 + base]      + x_i;
            float zf = zb[base + 8]  + zb[32 * 33 + base + 8]  + x_f;
            float zg = zb[base + 16] + zb[32 * 33 + base + 16] + x_g;
            float zo = zb[base + 24] + zb[32 * 33 + base + 24] + x_o;

            float iv = 1.f / (1.f + __expf(-zi));
            float fv = 1.f / (1.f + __expf(-zf));
            float eg = __expf(-2.f * zg); float gv = (1.f - eg) / (1.f + eg);
            float ov = 1.f / (1.f + __expf(-zo));
            c_reg = fv * c_reg + iv * gv;
            float ec = __expf(-2.f * c_reg); float tc = (1.f - ec) / (1.f + ec);
            float hv = ov * tc;

            g_H16[(hrow + t) * H_ + u0 + ej] = __float2half_rn(hv);
        }

        __syncthreads();
        if (tid == 0) red_rel_add(&g_flag[grp], 1u);   // arrival for step t
    }
}

// ---------------------------------------------------------------------------
extern "C" void kernel_launch(void* const* d_in, const int* in_sizes, int n_in,
                              void* d_out, int out_size)
{
    const float* obs = (const float*)d_in[0];
    const float* W1x = (const float*)d_in[1];
    const float* W1h = (const float*)d_in[2];
    const float* b1  = (const float*)d_in[3];
    const float* W2x = (const float*)d_in[4];
    const float* W2h = (const float*)d_in[5];
    const float* b2  = (const float*)d_in[6];
    const float* Wm  = (const float*)d_in[7];
    const float* bm  = (const float*)d_in[8];
    const float* Wc  = (const float*)d_in[9];
    const float* bc  = (const float*)d_in[10];

    float* XZ;
    __half *H16, *w2xh, *wmh, *wml, *wch, *wcl;
    __nv_bfloat16 *obsh, *obsl, *w1xh, *w1xl;
    cudaGetSymbolAddress((void**)&XZ,   g_XZ);
    cudaGetSymbolAddress((void**)&H16,  g_H16);
    cudaGetSymbolAddress((void**)&obsh, g_obs_h);
    cudaGetSymbolAddress((void**)&obsl, g_obs_l);
    cudaGetSymbolAddress((void**)&w1xh, g_W1x_h);
    cudaGetSymbolAddress((void**)&w1xl, g_W1x_l);
    cudaGetSymbolAddress((void**)&w2xh, g_W2x_h);
    cudaGetSymbolAddress((void**)&wmh,  g_Wm_h);
    cudaGetSymbolAddress((void**)&wml,  g_Wm_l);
    cudaGetSymbolAddress((void**)&wch,  g_Wc_h);
    cudaGetSymbolAddress((void**)&wcl,  g_Wc_l);

    float* out = (float*)d_out;
    size_t half = (size_t)out_size / 2;   // mean | cov

    cudaFuncSetAttribute(lstm_layer_mma,
                         cudaFuncAttributeMaxDynamicSharedMemorySize, SMEM_R);

    // ---- conversions
    conv_hl  <<<(BT_*DIN_/4 + 255)/256, 256>>>(obs, obsh, obsl, BT_*DIN_/4);
    conv_hl  <<<(DIN_*FH_/4 + 255)/256, 256>>>(W1x, w1xh, w1xl, DIN_*FH_/4);
    conv_f16 <<<(H_*FH_/4   + 255)/256, 256>>>(W2x, w2xh, H_*FH_/4);
    conv_hl16<<<(H_*DOUT_/4 + 255)/256, 256>>>(Wm,  wmh,  wml,  H_*DOUT_/4);
    conv_hl16<<<(H_*DOUT_/4 + 255)/256, 256>>>(Wc,  wch,  wcl,  H_*DOUT_/4);

    // XZ1 = obs @ W1x + b1   (bf16 3-term, full input precision)
    gemm_bf16_hl<0><<<dim3(FH_/64, BT_/128), 256>>>(obsh, obsl, w1xh, w1xl, b1, XZ,
                                                    BT_, FH_, DIN_, FH_);

    // Layer 1 recurrence -> g_H16 = H1 (fp16)
    zero_flags<<<1, 32>>>();
    lstm_layer_mma<<<NBLK_, NTH_R, SMEM_R>>>(W1h, XZ);

    // XZ2 = H1 @ W2x + b2   (fp16 A, single fp16 W)
    gemm_f16<0, 1><<<dim3(FH_/128, BT_/128), 256>>>(H16, w2xh, nullptr, b2, XZ,
                                                    BT_, FH_, H_, FH_);

    // Layer 2 recurrence -> g_H16 = H2
    zero_flags<<<1, 32>>>();
    lstm_layer_mma<<<NBLK_, NTH_R, SMEM_R>>>(W2h, XZ);

    // Heads: mean = H2@Wm + bm ; cov = softplus(H2@Wc + bc)  (hi/lo W)
    gemm_f16<0, 2><<<dim3(DOUT_/128, BT_/128), 256>>>(H16, wmh, wml, bm, out,
                                                      BT_, DOUT_, H_, DOUT_);
    gemm_f16<1, 2><<<dim3(DOUT_/128, BT_/128), 256>>>(H16, wch, wcl, bc, out + half,
                                                      BT_, DOUT_, H_, DOUT_);
}